// round 11
// baseline (speedup 1.0000x reference)
#include <cuda_runtime.h>
#include <cuda_bf16.h>
#include <stdint.h>

#define NEG_INF (__int_as_float(0xff800000))

#define Bc 2
#define Sc 4096
#define Ec 768
#define Hc 12
#define HDc 64
#define Wc 256
#define Gc 32
#define Mrows (Bc*Sc)   /* 8192 */

// ---------------- scratch (device globals; no allocation allowed) ----------------
__device__ float g_q [Mrows*Ec];
__device__ float g_k [Mrows*Ec];
__device__ float g_v [Mrows*Ec];
__device__ float g_kg[Mrows*Ec];
__device__ float g_vg[Mrows*Ec];
__device__ float g_qg[Bc*Gc*Ec];
__device__ float g_gw[(size_t)Bc*Hc*Gc*Sc];
__device__ float g_gattn[Bc*Gc*Ec];

// bf16 split scratch (uint4 arrays for guaranteed 16B alignment)
__device__ uint4 g_xh4[(size_t)Mrows*Ec/8];
__device__ uint4 g_xl4[(size_t)Mrows*Ec/8];
__device__ uint4 g_wth4[(size_t)5*Ec*Ec/8];
__device__ uint4 g_wtl4[(size_t)5*Ec*Ec/8];

// ---------------- bf16 mma helper (legacy mma.sync, valid on compute_103) ----------------
__device__ __forceinline__ void mma_bf16(float* d, const uint32_t* a, const uint32_t* b) {
    asm volatile(
        "mma.sync.aligned.m16n8k16.row.col.f32.bf16.bf16.f32 "
        "{%0,%1,%2,%3},{%4,%5,%6,%7},{%8,%9},{%0,%1,%2,%3};"
        : "+f"(d[0]), "+f"(d[1]), "+f"(d[2]), "+f"(d[3])
        : "r"(a[0]), "r"(a[1]), "r"(a[2]), "r"(a[3]), "r"(b[0]), "r"(b[1]));
}

// ---------------- 0a) split x -> bf16 hi/lo ----------------
__global__ __launch_bounds__(256) void split_x(const float* __restrict__ x)
{
    const int i = (blockIdx.x * 256 + threadIdx.x) * 4;
    float4 v = *(const float4*)&x[i];
    __nv_bfloat16 hx = __float2bfloat16_rn(v.x);
    __nv_bfloat16 hy = __float2bfloat16_rn(v.y);
    __nv_bfloat16 hz = __float2bfloat16_rn(v.z);
    __nv_bfloat16 hw = __float2bfloat16_rn(v.w);
    __nv_bfloat16 lx = __float2bfloat16_rn(v.x - __bfloat162float(hx));
    __nv_bfloat16 ly = __float2bfloat16_rn(v.y - __bfloat162float(hy));
    __nv_bfloat16 lz = __float2bfloat16_rn(v.z - __bfloat162float(hz));
    __nv_bfloat16 lw = __float2bfloat16_rn(v.w - __bfloat162float(hw));
    __nv_bfloat162* ph = (__nv_bfloat162*)g_xh4;
    __nv_bfloat162* pl = (__nv_bfloat162*)g_xl4;
    ph[i/2]     = __nv_bfloat162(hx, hy);
    ph[i/2 + 1] = __nv_bfloat162(hz, hw);
    pl[i/2]     = __nv_bfloat162(lx, ly);
    pl[i/2 + 1] = __nv_bfloat162(lz, lw);
}

// ---------------- 0b) transpose + split W -> wT[n][k] bf16 hi/lo ----------------
__global__ __launch_bounds__(256) void split_wt(
    const float* __restrict__ w0, const float* __restrict__ w1,
    const float* __restrict__ w2, const float* __restrict__ w3,
    const float* __restrict__ w4)
{
    const int z = blockIdx.z;
    const float* W;
    switch (z) {
      case 0: W = w0; break; case 1: W = w1; break; case 2: W = w2; break;
      case 3: W = w3; break; default: W = w4; break;
    }
    __shared__ float tile[32][33];
    const int k0 = blockIdx.x * 32;
    const int n0 = blockIdx.y * 32;
    const int t = threadIdx.x;
    const int tx = t & 31, ty = t >> 5;
    #pragma unroll
    for (int i = 0; i < 4; i++)
        tile[ty + 8*i][tx] = W[(size_t)(k0 + ty + 8*i) * Ec + n0 + tx];
    __syncthreads();
    __nv_bfloat16* oh = (__nv_bfloat16*)g_wth4 + (size_t)z * Ec * Ec;
    __nv_bfloat16* ol = (__nv_bfloat16*)g_wtl4 + (size_t)z * Ec * Ec;
    #pragma unroll
    for (int i = 0; i < 4; i++) {
        const float v = tile[tx][ty + 8*i];
        const __nv_bfloat16 h = __float2bfloat16_rn(v);
        const __nv_bfloat16 l = __float2bfloat16_rn(v - __bfloat162float(h));
        oh[(size_t)(n0 + ty + 8*i) * Ec + k0 + tx] = h;
        ol[(size_t)(n0 + ty + 8*i) * Ec + k0 + tx] = l;
    }
}

// ---------------- 1) projection GEMMs: bf16 m16n8k16 3-term split ----------------
#define SSTR2 136
#define KT 32

__global__ __launch_bounds__(256) void proj_bf16(
    const float* __restrict__ b0, const float* __restrict__ b1,
    const float* __restrict__ b2, const float* __restrict__ b3,
    const float* __restrict__ b4)
{
    const int z  = blockIdx.z;
    const float* bias; float* out; float scale = 1.0f;
    switch (z) {
      case 0: bias = b0; out = g_q;  scale = 0.125f; break;
      case 1: bias = b1; out = g_k;  break;
      case 2: bias = b2; out = g_v;  break;
      case 3: bias = b3; out = g_kg; break;
      default:bias = b4; out = g_vg; break;
    }
    const int m0 = blockIdx.y * 128;
    const int n0 = blockIdx.x * 128;

    const char* Axh = (const char*)g_xh4;
    const char* Axl = (const char*)g_xl4;
    const char* Bwh = (const char*)g_wth4 + (size_t)z * Ec * Ec * 2;
    const char* Bwl = (const char*)g_wtl4 + (size_t)z * Ec * Ec * 2;

    __shared__ uint32_t Ah2[16][SSTR2];
    __shared__ uint32_t Al2[16][SSTR2];
    __shared__ uint32_t Bh2[16][SSTR2];
    __shared__ uint32_t Bl2[16][SSTR2];

    const int t    = threadIdx.x;
    const int lane = t & 31;
    const int warp = t >> 5;
    const int gid  = lane >> 2;
    const int tig  = lane & 3;
    const int mbase = (warp & 1) * 64;
    const int nbase = (warp >> 1) * 32;

    const int r0 = t >> 2,        kq0 = t & 3;
    const int r1 = (t + 256) >> 2, kq1 = (t + 256) & 3;

    const char* pAh0 = Axh + ((size_t)(m0 + r0) * Ec + kq0 * 8) * 2;
    const char* pAh1 = Axh + ((size_t)(m0 + r1) * Ec + kq1 * 8) * 2;
    const char* pAl0 = Axl + ((size_t)(m0 + r0) * Ec + kq0 * 8) * 2;
    const char* pAl1 = Axl + ((size_t)(m0 + r1) * Ec + kq1 * 8) * 2;
    const char* pBh0 = Bwh + ((size_t)(n0 + r0) * Ec + kq0 * 8) * 2;
    const char* pBh1 = Bwh + ((size_t)(n0 + r1) * Ec + kq1 * 8) * 2;
    const char* pBl0 = Bwl + ((size_t)(n0 + r0) * Ec + kq0 * 8) * 2;
    const char* pBl1 = Bwl + ((size_t)(n0 + r1) * Ec + kq1 * 8) * 2;

    float acc[4][4][4];
    #pragma unroll
    for (int mt = 0; mt < 4; mt++)
      #pragma unroll
      for (int nt = 0; nt < 4; nt++)
        #pragma unroll
        for (int i = 0; i < 4; i++) acc[mt][nt][i] = 0.0f;

    uint4 vAh0 = *(const uint4*)pAh0, vAh1 = *(const uint4*)pAh1;
    uint4 vAl0 = *(const uint4*)pAl0, vAl1 = *(const uint4*)pAl1;
    uint4 vBh0 = *(const uint4*)pBh0, vBh1 = *(const uint4*)pBh1;
    uint4 vBl0 = *(const uint4*)pBl0, vBl1 = *(const uint4*)pBl1;

    for (int kt = 0; kt < Ec; kt += KT) {
        __syncthreads();
        {
            const int rr0 = kq0 * 4, rr1 = kq1 * 4;
            Ah2[rr0 + 0][r0] = vAh0.x; Ah2[rr0 + 1][r0] = vAh0.y;
            Ah2[rr0 + 2][r0] = vAh0.z; Ah2[rr0 + 3][r0] = vAh0.w;
            Ah2[rr1 + 0][r1] = vAh1.x; Ah2[rr1 + 1][r1] = vAh1.y;
            Ah2[rr1 + 2][r1] = vAh1.z; Ah2[rr1 + 3][r1] = vAh1.w;
            Al2[rr0 + 0][r0] = vAl0.x; Al2[rr0 + 1][r0] = vAl0.y;
            Al2[rr0 + 2][r0] = vAl0.z; Al2[rr0 + 3][r0] = vAl0.w;
            Al2[rr1 + 0][r1] = vAl1.x; Al2[rr1 + 1][r1] = vAl1.y;
            Al2[rr1 + 2][r1] = vAl1.z; Al2[rr1 + 3][r1] = vAl1.w;
            Bh2[rr0 + 0][r0] = vBh0.x; Bh2[rr0 + 1][r0] = vBh0.y;
            Bh2[rr0 + 2][r0] = vBh0.z; Bh2[rr0 + 3][r0] = vBh0.w;
            Bh2[rr1 + 0][r1] = vBh1.x; Bh2[rr1 + 1][r1] = vBh1.y;
            Bh2[rr1 + 2][r1] = vBh1.z; Bh2[rr1 + 3][r1] = vBh1.w;
            Bl2[rr0 + 0][r0] = vBl0.x; Bl2[rr0 + 1][r0] = vBl0.y;
            Bl2[rr0 + 2][r0] = vBl0.z; Bl2[rr0 + 3][r0] = vBl0.w;
            Bl2[rr1 + 0][r1] = vBl1.x; Bl2[rr1 + 1][r1] = vBl1.y;
            Bl2[rr1 + 2][r1] = vBl1.z; Bl2[rr1 + 3][r1] = vBl1.w;
        }
        __syncthreads();

        if (kt + KT < Ec) {
            const int koff = (kt + KT) * 2;
            vAh0 = *(const uint4*)(pAh0 + koff); vAh1 = *(const uint4*)(pAh1 + koff);
            vAl0 = *(const uint4*)(pAl0 + koff); vAl1 = *(const uint4*)(pAl1 + koff);
            vBh0 = *(const uint4*)(pBh0 + koff); vBh1 = *(const uint4*)(pBh1 + koff);
            vBl0 = *(const uint4*)(pBl0 + koff); vBl1 = *(const uint4*)(pBl1 + koff);
        }

        #pragma unroll
        for (int s16 = 0; s16 < 2; s16++) {
            const int kb = s16 * 8;
            uint32_t ah[4][4], al[4][4], bh[4][2], bl[4][2];
            #pragma unroll
            for (int mt = 0; mt < 4; mt++) {
                const int m = mbase + mt * 16 + gid;
                ah[mt][0] = Ah2[kb + tig][m];
                ah[mt][1] = Ah2[kb + tig][m + 8];
                ah[mt][2] = Ah2[kb + tig + 4][m];
                ah[mt][3] = Ah2[kb + tig + 4][m + 8];
                al[mt][0] = Al2[kb + tig][m];
                al[mt][1] = Al2[kb + tig][m + 8];
                al[mt][2] = Al2[kb + tig + 4][m];
                al[mt][3] = Al2[kb + tig + 4][m + 8];
            }
            #pragma unroll
            for (int nt = 0; nt < 4; nt++) {
                const int n = nbase + nt * 8 + gid;
                bh[nt][0] = Bh2[kb + tig][n];
                bh[nt][1] = Bh2[kb + tig + 4][n];
                bl[nt][0] = Bl2[kb + tig][n];
                bl[nt][1] = Bl2[kb + tig + 4][n];
            }
            #pragma unroll
            for (int mt = 0; mt < 4; mt++)
              #pragma unroll
              for (int nt = 0; nt < 4; nt++) {
                  mma_bf16(acc[mt][nt], ah[mt], bh[nt]);
                  mma_bf16(acc[mt][nt], ah[mt], bl[nt]);
                  mma_bf16(acc[mt][nt], al[mt], bh[nt]);
              }
        }
    }

    #pragma unroll
    for (int mt = 0; mt < 4; mt++) {
        const int r = m0 + mbase + mt * 16 + gid;
        #pragma unroll
        for (int nt = 0; nt < 4; nt++) {
            const int c = n0 + nbase + nt * 8 + 2 * tig;
            const float bb0 = bias[c], bb1 = bias[c + 1];
            float2 o0 = make_float2((acc[mt][nt][0] + bb0) * scale,
                                    (acc[mt][nt][1] + bb1) * scale);
            float2 o1 = make_float2((acc[mt][nt][2] + bb0) * scale,
                                    (acc[mt][nt][3] + bb1) * scale);
            *(float2*)&out[(size_t)r * Ec + c] = o0;
            *(float2*)&out[(size_t)(r + 8) * Ec + c] = o1;
        }
    }
}

// ---------------- 2) qg: grid (6 col-chunks, 64 rows), 128 thr, 8x unroll ----------------
__global__ __launch_bounds__(128) void qg_gemm(const float* __restrict__ x,
                                               const float* __restrict__ w,
                                               const float* __restrict__ bias)
{
    const int m  = blockIdx.y;          // 0..63
    const int b  = m >> 5, g = m & 31;
    const int c  = blockIdx.x * 128 + threadIdx.x;
    const float* xr = x + (size_t)(b * Sc + g) * Ec;
    __shared__ float xs[Ec];
    const int t = threadIdx.x;
    #pragma unroll
    for (int i = 0; i < 6; i++) xs[t + 128 * i] = xr[t + 128 * i];
    __syncthreads();
    float acc = 0.0f;
    #pragma unroll 8
    for (int k = 0; k < Ec; k++)
        acc += xs[k] * __ldg(&w[(size_t)k * Ec + c]);
    g_qg[(size_t)m * Ec + c] = (acc + bias[c]) * 0.125f;
}

// ---------------- 3) banded + global flash attention ----------------
__global__ __launch_bounds__(256) void flash_banded(const int* __restrict__ mask,
                                                    float* __restrict__ out)
{
    const int q0 = blockIdx.x * 64;
    const int h  = blockIdx.y;
    const int b  = blockIdx.z;

    __shared__ float Qs[64 * 64];   // [d][r]
    __shared__ float KPs[64 * 64];  // K as [d][c], then reused as P [r][c]
    __shared__ float Vs[64 * 64];   // [c][d]

    const int t    = threadIdx.x;
    const int tx   = t & 15, ty = t >> 4;
    const int lane = t & 31, wrp = t >> 5;

    {
        const int lr = t >> 2, ld = (t & 3) * 16;
        const float* qp = g_q + (size_t)(b * Sc + q0 + lr) * Ec + h * 64 + ld;
        #pragma unroll
        for (int u = 0; u < 4; u++) {
            float4 v = *(const float4*)(qp + 4 * u);
            Qs[(ld + 4 * u + 0) * 64 + lr] = v.x;
            Qs[(ld + 4 * u + 1) * 64 + lr] = v.y;
            Qs[(ld + 4 * u + 2) * 64 + lr] = v.z;
            Qs[(ld + 4 * u + 3) * 64 + lr] = v.w;
        }
    }

    float m8[8], l8[8];
    #pragma unroll
    for (int i = 0; i < 8; i++) { m8[i] = NEG_INF; l8[i] = 0.0f; }
    float O[4][4];
    #pragma unroll
    for (int i = 0; i < 4; i++)
      #pragma unroll
      for (int j = 0; j < 4; j++) O[i][j] = 0.0f;

    for (int tt = 0; tt < 10; tt++) {
        const bool is_sel = (tt == 0);
        const int tstart = is_sel ? 0 : (q0 - Wc + (tt - 1) * 64);

        __syncthreads();
        {
            const int lr = t >> 2, ld = (t & 3) * 16;
            const int p = tstart + lr;
            if (p >= 0 && p < Sc) {
                const float* kp = g_k + (size_t)(b * Sc + p) * Ec + h * 64 + ld;
                const float* vp = g_v + (size_t)(b * Sc + p) * Ec + h * 64 + ld;
                #pragma unroll
                for (int u = 0; u < 4; u++) {
                    float4 kv = *(const float4*)(kp + 4 * u);
                    KPs[(ld + 4 * u + 0) * 64 + lr] = kv.x;
                    KPs[(ld + 4 * u + 1) * 64 + lr] = kv.y;
                    KPs[(ld + 4 * u + 2) * 64 + lr] = kv.z;
                    KPs[(ld + 4 * u + 3) * 64 + lr] = kv.w;
                    *(float4*)&Vs[lr * 64 + ld + 4 * u] = *(const float4*)(vp + 4 * u);
                }
            } else {
                const float4 z4 = make_float4(0.f, 0.f, 0.f, 0.f);
                #pragma unroll
                for (int u = 0; u < 4; u++) {
                    KPs[(ld + 4 * u + 0) * 64 + lr] = 0.f;
                    KPs[(ld + 4 * u + 1) * 64 + lr] = 0.f;
                    KPs[(ld + 4 * u + 2) * 64 + lr] = 0.f;
                    KPs[(ld + 4 * u + 3) * 64 + lr] = 0.f;
                    *(float4*)&Vs[lr * 64 + ld + 4 * u] = z4;
                }
            }
        }
        __syncthreads();

        float s[4][4];
        #pragma unroll
        for (int i = 0; i < 4; i++)
          #pragma unroll
          for (int j = 0; j < 4; j++) s[i][j] = 0.0f;
        #pragma unroll
        for (int d = 0; d < 64; d++) {
            float4 q4 = *(const float4*)&Qs[d * 64 + ty * 4];
            float4 k4 = *(const float4*)&KPs[d * 64 + tx * 4];
            float qa[4] = {q4.x, q4.y, q4.z, q4.w};
            float ka[4] = {k4.x, k4.y, k4.z, k4.w};
            #pragma unroll
            for (int i = 0; i < 4; i++)
              #pragma unroll
              for (int j = 0; j < 4; j++) s[i][j] += qa[i] * ka[j];
        }
        __syncthreads();
        #pragma unroll
        for (int i = 0; i < 4; i++)
            *(float4*)&KPs[(ty * 4 + i) * 64 + tx * 4] =
                make_float4(s[i][0], s[i][1], s[i][2], s[i][3]);
        __syncthreads();

        const int c1 = lane, c2 = lane + 32;
        float bias1 = 0.f, bias2 = 0.f;
        bool v1base, v2base;
        if (is_sel) {
            v1base = (c1 < Gc);
            v2base = false;
        } else {
            const int p1 = tstart + c1, p2 = tstart + c2;
            v1base = (p1 >= 0 && p1 < Sc);
            v2base = (p2 >= 0 && p2 < Sc);
            if (v1base && mask[b * Sc + p1] != 0) bias1 = -10000.0f;
            if (v2base && mask[b * Sc + p2] != 0) bias2 = -10000.0f;
        }
        float alpha8[8];
        #pragma unroll
        for (int rr = 0; rr < 8; rr++) {
            const int r = wrp * 8 + rr;
            float s1 = KPs[r * 64 + c1];
            float s2 = KPs[r * 64 + c2];
            bool bv1 = v1base, bv2 = v2base;
            if (!is_sel) {
                const int qi = q0 + r;
                const int p1 = tstart + c1, p2 = tstart + c2;
                bv1 = v1base && (p1 >= qi - Wc) && (p1 <= qi + Wc);
                bv2 = v2base && (p2 >= qi - Wc) && (p2 <= qi + Wc);
            }
            s1 = bv1 ? (s1 + bias1) : NEG_INF;
            s2 = bv2 ? (s2 + bias2) : NEG_INF;
            float tmax = fmaxf(s1, s2);
            #pragma unroll
            for (int o = 16; o; o >>= 1) tmax = fmaxf(tmax, __shfl_xor_sync(0xffffffffu, tmax, o));
            const float mnew = fmaxf(m8[rr], tmax);
            const float a = __expf(m8[rr] - mnew);
            const float p1e = __expf(s1 - mnew);
            const float p2e = __expf(s2 - mnew);
            KPs[r * 64 + c1] = p1e;
            KPs[r * 64 + c2] = p2e;
            float tsum = p1e + p2e;
            #pragma unroll
            for (int o = 16; o; o >>= 1) tsum += __shfl_xor_sync(0xffffffffu, tsum, o);
            l8[rr] = l8[rr] * a + tsum;
            m8[rr] = mnew;
            alpha8[rr] = a;
        }
        __syncthreads();

        #pragma unroll
        for (int i = 0; i < 4; i++) {
            const float a = (ty & 1) ? alpha8[i + 4] : alpha8[i];
            #pragma unroll
            for (int j = 0; j < 4; j++) O[i][j] *= a;
        }
        #pragma unroll
        for (int c = 0; c < 64; c++) {
            float4 v4 = *(const float4*)&Vs[c * 64 + tx * 4];
            #pragma unroll
            for (int i = 0; i < 4; i++) {
                const float pv = KPs[(ty * 4 + i) * 64 + c];
                O[i][0] += pv * v4.x;
                O[i][1] += pv * v4.y;
                O[i][2] += pv * v4.z;
                O[i][3] += pv * v4.w;
            }
        }
    }

    #pragma unroll
    for (int i = 0; i < 4; i++) {
        const float linv = 1.0f / ((ty & 1) ? l8[i + 4] : l8[i]);
        float4 o4 = make_float4(O[i][0] * linv, O[i][1] * linv, O[i][2] * linv, O[i][3] * linv);
        *(float4*)&out[(size_t)(b * Sc + q0 + ty * 4 + i) * Ec + h * 64 + tx * 4] = o4;
    }
}

// ---------------- 4) global scores ----------------
__global__ __launch_bounds__(256) void global_scores()
{
    const int st = blockIdx.x;
    const int h  = blockIdx.y;
    const int b  = blockIdx.z;
    __shared__ float qgs[64 * 32];
    __shared__ float kgs[64 * 128];
    const int t = threadIdx.x;
    {
        const int g = t >> 3, d0 = (t & 7) * 8;
        const float* qp = g_qg + (size_t)(b * Gc + g) * Ec + h * 64 + d0;
        float4 v0 = *(const float4*)qp;
        float4 v1 = *(const float4*)(qp + 4);
        qgs[(d0 + 0) * 32 + g] = v0.x; qgs[(d0 + 1) * 32 + g] = v0.y;
        qgs[(d0 + 2) * 32 + g] = v0.z; qgs[(d0 + 3) * 32 + g] = v0.w;
        qgs[(d0 + 4) * 32 + g] = v1.x; qgs[(d0 + 5) * 32 + g] = v1.y;
        qgs[(d0 + 6) * 32 + g] = v1.z; qgs[(d0 + 7) * 32 + g] = v1.w;
    }
    {
        const int c = t >> 1, d0 = (t & 1) * 32;
        const int p = st * 128 + c;
        const float* kp = g_kg + (size_t)(b * Sc + p) * Ec + h * 64 + d0;
        #pragma unroll
        for (int u = 0; u < 8; u++) {
            float4 v = *(const float4*)(kp + 4 * u);
            kgs[(d0 + 4 * u + 0) * 128 + c] = v.x;
            kgs[(d0 + 4 * u + 1) * 128 + c] = v.y;
            kgs[(d0 + 4 * u + 2) * 128 + c] = v.z;
            kgs[(d0 + 4 * u + 3) * 128 + c] = v.w;
        }
    }
    __syncthreads();
    const int tx = t & 31, ty = t >> 5;
    float s[4][4];
    #pragma unroll
    for (int i = 0; i < 4; i++)
      #pragma unroll
      for (int j = 0; j < 4; j++) s[i][j] = 0.0f;
    #pragma unroll
    for (int d = 0; d < 64; d++) {
        float4 q4 = *(const float4*)&qgs[d * 32 + ty * 4];
        float4 k4 = *(const float4*)&kgs[d * 128 + tx * 4];
        float qa[4] = {q4.x, q4.y, q4.z, q4.w};
        float ka[4] = {k4.x, k4.y, k4.z, k4.w};
        #pragma unroll
        for (int i = 0; i < 4; i++)
          #pragma unroll
          for (int j = 0; j < 4; j++) s[i][j] += qa[i] * ka[j];
    }
    #pragma unroll
    for (int i = 0; i < 4; i++) {
        const int g = ty * 4 + i;
        float* gp = g_gw + (((size_t)(b * Hc + h) * Gc + g) * Sc) + st * 128 + tx * 4;
        *(float4*)gp = make_float4(s[i][0], s[i][1], s[i][2], s[i][3]);
    }
}

// ---------------- 5) row softmax over S for gw ----------------
__global__ __launch_bounds__(256) void global_softmax()
{
    float* p = g_gw + (size_t)blockIdx.x * Sc;
    __shared__ float sm[8];
    const int t = threadIdx.x, lane = t & 31, wrp = t >> 5;
    float mx = NEG_INF;
    for (int i = t; i < Sc; i += 256) mx = fmaxf(mx, p[i]);
    #pragma unroll
    for (int o = 16; o; o >>= 1) mx = fmaxf(mx, __shfl_xor_sync(0xffffffffu, mx, o));
    if (lane == 0) sm[wrp] = mx;
    __syncthreads();
    mx = sm[0];
    #pragma unroll
    for (int i = 1; i < 8; i++) mx = fmaxf(mx, sm[i]);
    __syncthreads();
    float sum = 0.0f;
    for (int i = t; i < Sc; i += 256) {
        const float e = __expf(p[i] - mx);
        p[i] = e;
        sum += e;
    }
    #pragma unroll
    for (int o = 16; o; o >>= 1) sum += __shfl_xor_sync(0xffffffffu, sum, o);
    if (lane == 0) sm[wrp] = sum;
    __syncthreads();
    sum = 0.0f;
    #pragma unroll
    for (int i = 0; i < 8; i++) sum += sm[i];
    const float inv = 1.0f / sum;
    for (int i = t; i < Sc; i += 256) p[i] *= inv;
}

// ---------------- 6) zero gattn accumulator ----------------
__global__ void zero_gattn()
{
    const int idx = blockIdx.x * 256 + threadIdx.x;
    if (idx < Bc * Gc * Ec) g_gattn[idx] = 0.0f;
}

// ---------------- 7) global PV ----------------
__global__ __launch_bounds__(256) void global_pv()
{
    const int sc = blockIdx.x;
    const int h  = blockIdx.y;
    const int b  = blockIdx.z;
    __shared__ float ps[32 * 128];
    const int t  = threadIdx.x;
    const int d  = t & 63;
    const int gq = t >> 6;
    float acc[8];
    #pragma unroll
    for (int gi = 0; gi < 8; gi++) acc[gi] = 0.0f;

    for (int s0 = sc * 512; s0 < sc * 512 + 512; s0 += 128) {
        __syncthreads();
        {
            const int g = t >> 3, sl = (t & 7) * 16;
            const float* src = g_gw + ((size_t)(b * Hc + h) * Gc + g) * Sc + s0 + sl;
            #pragma unroll
            for (int u = 0; u < 4; u++)
                *(float4*)&ps[g * 128 + sl + 4 * u] = *(const float4*)(src + 4 * u);
        }
        __syncthreads();
        for (int sl = 0; sl < 128; sl++) {
            const float vv = g_vg[(size_t)(b * Sc + s0 + sl) * Ec + h * 64 + d];
            #pragma unroll
            for (int gi = 0; gi < 8; gi++)
                acc[gi] += ps[(gq * 8 + gi) * 128 + sl] * vv;
        }
    }
    #pragma unroll
    for (int gi = 0; gi < 8; gi++)
        atomicAdd(&g_gattn[(size_t)(b * Gc + gq * 8 + gi) * Ec + h * 64 + d], acc[gi]);
}

// ---------------- 8) overwrite out[:, :G] with gattn ----------------
__global__ void write_global_rows(float* __restrict__ out)
{
    const int idx = blockIdx.x * 256 + threadIdx.x;
    if (idx < Bc * Gc * Ec) {
        const int e = idx % Ec;
        const int m = idx / Ec;
        const int b = m / Gc, g = m % Gc;
        out[(size_t)(b * Sc + g) * Ec + e] = g_gattn[idx];
    }
}

// ---------------- launch ----------------
extern "C" void kernel_launch(void* const* d_in, const int* in_sizes, int n_in,
                              void* d_out, int out_size)
{
    (void)out_size;
    const float* x    = (const float*)d_in[0];
    const int*   mask = (const int*)d_in[1];
    int wi = 2;
    if (n_in > 2 && in_sizes[2] == 1) wi = 3;
    const float* wq  = (const float*)d_in[wi + 0];
    const float* bq  = (const float*)d_in[wi + 1];
    const float* wk  = (const float*)d_in[wi + 2];
    const float* bk  = (const float*)d_in[wi + 3];
    const float* wv  = (const float*)d_in[wi + 4];
    const float* bv  = (const float*)d_in[wi + 5];
    const float* wqg = (const float*)d_in[wi + 6];
    const float* bqg = (const float*)d_in[wi + 7];
    const float* wkg = (const float*)d_in[wi + 8];
    const float* bkg = (const float*)d_in[wi + 9];
    const float* wvg = (const float*)d_in[wi + 10];
    const float* bvg = (const float*)d_in[wi + 11];
    float* out = (float*)d_out;

    split_x<<<(Mrows * Ec) / 1024, 256>>>(x);
    split_wt<<<dim3(Ec / 32, Ec / 32, 5), 256>>>(wq, wk, wv, wkg, wvg);
    proj_bf16<<<dim3(Ec / 128, Mrows / 128, 5), 256>>>(bq, bk, bv, bkg, bvg);
    qg_gemm<<<dim3(Ec / 128, Bc * Gc), 128>>>(x, wqg, bqg);

    dim3 gF(Sc / 64, Hc, Bc);
    flash_banded<<<gF, 256>>>(mask, out);

    dim3 gGS(Sc / 128, Hc, Bc);
    global_scores<<<gGS, 256>>>();
    global_softmax<<<Bc * Hc * Gc, 256>>>();
    zero_gattn<<<(Bc * Gc * Ec + 255) / 256, 256>>>();
    dim3 gPV(8, Hc, Bc);
    global_pv<<<gPV, 256>>>();
    write_global_rows<<<(Bc * Gc * Ec + 255) / 256, 256>>>(out);
}

// round 13
// speedup vs baseline: 1.9456x; 1.9456x over previous
#include <cuda_runtime.h>
#include <cuda_bf16.h>
#include <stdint.h>

#define NEG_INF (__int_as_float(0xff800000))

#define Bc 2
#define Sc 4096
#define Ec 768
#define Hc 12
#define HDc 64
#define Wc 256
#define Gc 32
#define Mrows (Bc*Sc)   /* 8192 */

// ---------------- scratch (device globals; no allocation allowed) ----------------
__device__ float g_kg[Mrows*Ec];
__device__ float g_vg[Mrows*Ec];
__device__ float g_qg[Bc*Gc*Ec];
__device__ float g_gw[(size_t)Bc*Hc*Gc*Sc];
__device__ float g_gattn[Bc*Gc*Ec];

// bf16 split scratch (uint4 arrays for guaranteed 16B alignment)
__device__ uint4 g_xh4[(size_t)Mrows*Ec/8];
__device__ uint4 g_xl4[(size_t)Mrows*Ec/8];
__device__ uint4 g_wth4[(size_t)5*Ec*Ec/8];
__device__ uint4 g_wtl4[(size_t)5*Ec*Ec/8];

// q/k/v bf16 hi/lo (packed bf16x2 words, [row][Ec] layout)
__device__ __align__(16) uint32_t g_qbh[(size_t)Mrows*Ec/2];
__device__ __align__(16) uint32_t g_qbl[(size_t)Mrows*Ec/2];
__device__ __align__(16) uint32_t g_kbh[(size_t)Mrows*Ec/2];
__device__ __align__(16) uint32_t g_kbl[(size_t)Mrows*Ec/2];
__device__ __align__(16) uint32_t g_vbh[(size_t)Mrows*Ec/2];
__device__ __align__(16) uint32_t g_vbl[(size_t)Mrows*Ec/2];
// V transposed: [b][h][d=64][s=Sc] bf16, s-pairs packed
__device__ __align__(16) uint32_t g_vth[(size_t)Bc*Hc*HDc*Sc/2];
__device__ __align__(16) uint32_t g_vtl[(size_t)Bc*Hc*HDc*Sc/2];

// ---------------- bf16 mma helper (legacy mma.sync, valid on compute_103) ----------------
__device__ __forceinline__ void mma_bf16(float* d, const uint32_t* a, const uint32_t* b) {
    asm volatile(
        "mma.sync.aligned.m16n8k16.row.col.f32.bf16.bf16.f32 "
        "{%0,%1,%2,%3},{%4,%5,%6,%7},{%8,%9},{%0,%1,%2,%3};"
        : "+f"(d[0]), "+f"(d[1]), "+f"(d[2]), "+f"(d[3])
        : "r"(a[0]), "r"(a[1]), "r"(a[2]), "r"(a[3]), "r"(b[0]), "r"(b[1]));
}

__device__ __forceinline__ void split2f(float a, float b, uint32_t& hw, uint32_t& lw) {
    const __nv_bfloat16 ha = __float2bfloat16_rn(a);
    const __nv_bfloat16 hb = __float2bfloat16_rn(b);
    const __nv_bfloat16 la = __float2bfloat16_rn(a - __bfloat162float(ha));
    const __nv_bfloat16 lb = __float2bfloat16_rn(b - __bfloat162float(hb));
    hw = ((uint32_t)*(const unsigned short*)&hb << 16) | *(const unsigned short*)&ha;
    lw = ((uint32_t)*(const unsigned short*)&lb << 16) | *(const unsigned short*)&la;
}

// ---------------- 0a) split x -> bf16 hi/lo ----------------
__global__ __launch_bounds__(256) void split_x(const float* __restrict__ x)
{
    const int i = (blockIdx.x * 256 + threadIdx.x) * 4;
    float4 v = *(const float4*)&x[i];
    __nv_bfloat16 hx = __float2bfloat16_rn(v.x);
    __nv_bfloat16 hy = __float2bfloat16_rn(v.y);
    __nv_bfloat16 hz = __float2bfloat16_rn(v.z);
    __nv_bfloat16 hw = __float2bfloat16_rn(v.w);
    __nv_bfloat16 lx = __float2bfloat16_rn(v.x - __bfloat162float(hx));
    __nv_bfloat16 ly = __float2bfloat16_rn(v.y - __bfloat162float(hy));
    __nv_bfloat16 lz = __float2bfloat16_rn(v.z - __bfloat162float(hz));
    __nv_bfloat16 lw = __float2bfloat16_rn(v.w - __bfloat162float(hw));
    __nv_bfloat162* ph = (__nv_bfloat162*)g_xh4;
    __nv_bfloat162* pl = (__nv_bfloat162*)g_xl4;
    ph[i/2]     = __nv_bfloat162(hx, hy);
    ph[i/2 + 1] = __nv_bfloat162(hz, hw);
    pl[i/2]     = __nv_bfloat162(lx, ly);
    pl[i/2 + 1] = __nv_bfloat162(lz, lw);
}

// ---------------- 0b) transpose + split W -> wT[n][k] bf16 hi/lo ----------------
__global__ __launch_bounds__(256) void split_wt(
    const float* __restrict__ w0, const float* __restrict__ w1,
    const float* __restrict__ w2, const float* __restrict__ w3,
    const float* __restrict__ w4)
{
    const int z = blockIdx.z;
    const float* W;
    switch (z) {
      case 0: W = w0; break; case 1: W = w1; break; case 2: W = w2; break;
      case 3: W = w3; break; default: W = w4; break;
    }
    __shared__ float tile[32][33];
    const int k0 = blockIdx.x * 32;
    const int n0 = blockIdx.y * 32;
    const int t = threadIdx.x;
    const int tx = t & 31, ty = t >> 5;
    #pragma unroll
    for (int i = 0; i < 4; i++)
        tile[ty + 8*i][tx] = W[(size_t)(k0 + ty + 8*i) * Ec + n0 + tx];
    __syncthreads();
    __nv_bfloat16* oh = (__nv_bfloat16*)g_wth4 + (size_t)z * Ec * Ec;
    __nv_bfloat16* ol = (__nv_bfloat16*)g_wtl4 + (size_t)z * Ec * Ec;
    #pragma unroll
    for (int i = 0; i < 4; i++) {
        const float v = tile[tx][ty + 8*i];
        const __nv_bfloat16 h = __float2bfloat16_rn(v);
        const __nv_bfloat16 l = __float2bfloat16_rn(v - __bfloat162float(h));
        oh[(size_t)(n0 + ty + 8*i) * Ec + k0 + tx] = h;
        ol[(size_t)(n0 + ty + 8*i) * Ec + k0 + tx] = l;
    }
}

// ---------------- 1) projection GEMMs: bf16 m16n8k16 3-term split ----------------
// z=0,1,2 (q,k,v): outputs bf16 hi/lo split; z=3,4 (kg,vg): fp32.
#define SSTR2 136
#define KT 32

__global__ __launch_bounds__(256) void proj_bf16(
    const float* __restrict__ b0, const float* __restrict__ b1,
    const float* __restrict__ b2, const float* __restrict__ b3,
    const float* __restrict__ b4)
{
    const int z  = blockIdx.z;
    const float* bias; float scale = 1.0f;
    switch (z) {
      case 0: bias = b0; scale = 0.125f; break;
      case 1: bias = b1; break;
      case 2: bias = b2; break;
      case 3: bias = b3; break;
      default:bias = b4; break;
    }
    const int m0 = blockIdx.y * 128;
    const int n0 = blockIdx.x * 128;

    const char* Axh = (const char*)g_xh4;
    const char* Axl = (const char*)g_xl4;
    const char* Bwh = (const char*)g_wth4 + (size_t)z * Ec * Ec * 2;
    const char* Bwl = (const char*)g_wtl4 + (size_t)z * Ec * Ec * 2;

    __shared__ uint32_t Ah2[16][SSTR2];
    __shared__ uint32_t Al2[16][SSTR2];
    __shared__ uint32_t Bh2[16][SSTR2];
    __shared__ uint32_t Bl2[16][SSTR2];

    const int t    = threadIdx.x;
    const int lane = t & 31;
    const int warp = t >> 5;
    const int gid  = lane >> 2;
    const int tig  = lane & 3;
    const int mbase = (warp & 1) * 64;
    const int nbase = (warp >> 1) * 32;

    const int r0 = t >> 2,        kq0 = t & 3;
    const int r1 = (t + 256) >> 2, kq1 = (t + 256) & 3;

    const char* pAh0 = Axh + ((size_t)(m0 + r0) * Ec + kq0 * 8) * 2;
    const char* pAh1 = Axh + ((size_t)(m0 + r1) * Ec + kq1 * 8) * 2;
    const char* pAl0 = Axl + ((size_t)(m0 + r0) * Ec + kq0 * 8) * 2;
    const char* pAl1 = Axl + ((size_t)(m0 + r1) * Ec + kq1 * 8) * 2;
    const char* pBh0 = Bwh + ((size_t)(n0 + r0) * Ec + kq0 * 8) * 2;
    const char* pBh1 = Bwh + ((size_t)(n0 + r1) * Ec + kq1 * 8) * 2;
    const char* pBl0 = Bwl + ((size_t)(n0 + r0) * Ec + kq0 * 8) * 2;
    const char* pBl1 = Bwl + ((size_t)(n0 + r1) * Ec + kq1 * 8) * 2;

    float acc[4][4][4];
    #pragma unroll
    for (int mt = 0; mt < 4; mt++)
      #pragma unroll
      for (int nt = 0; nt < 4; nt++)
        #pragma unroll
        for (int i = 0; i < 4; i++) acc[mt][nt][i] = 0.0f;

    uint4 vAh0 = *(const uint4*)pAh0, vAh1 = *(const uint4*)pAh1;
    uint4 vAl0 = *(const uint4*)pAl0, vAl1 = *(const uint4*)pAl1;
    uint4 vBh0 = *(const uint4*)pBh0, vBh1 = *(const uint4*)pBh1;
    uint4 vBl0 = *(const uint4*)pBl0, vBl1 = *(const uint4*)pBl1;

    for (int kt = 0; kt < Ec; kt += KT) {
        __syncthreads();
        {
            const int rr0 = kq0 * 4, rr1 = kq1 * 4;
            Ah2[rr0 + 0][r0] = vAh0.x; Ah2[rr0 + 1][r0] = vAh0.y;
            Ah2[rr0 + 2][r0] = vAh0.z; Ah2[rr0 + 3][r0] = vAh0.w;
            Ah2[rr1 + 0][r1] = vAh1.x; Ah2[rr1 + 1][r1] = vAh1.y;
            Ah2[rr1 + 2][r1] = vAh1.z; Ah2[rr1 + 3][r1] = vAh1.w;
            Al2[rr0 + 0][r0] = vAl0.x; Al2[rr0 + 1][r0] = vAl0.y;
            Al2[rr0 + 2][r0] = vAl0.z; Al2[rr0 + 3][r0] = vAl0.w;
            Al2[rr1 + 0][r1] = vAl1.x; Al2[rr1 + 1][r1] = vAl1.y;
            Al2[rr1 + 2][r1] = vAl1.z; Al2[rr1 + 3][r1] = vAl1.w;
            Bh2[rr0 + 0][r0] = vBh0.x; Bh2[rr0 + 1][r0] = vBh0.y;
            Bh2[rr0 + 2][r0] = vBh0.z; Bh2[rr0 + 3][r0] = vBh0.w;
            Bh2[rr1 + 0][r1] = vBh1.x; Bh2[rr1 + 1][r1] = vBh1.y;
            Bh2[rr1 + 2][r1] = vBh1.z; Bh2[rr1 + 3][r1] = vBh1.w;
            Bl2[rr0 + 0][r0] = vBl0.x; Bl2[rr0 + 1][r0] = vBl0.y;
            Bl2[rr0 + 2][r0] = vBl0.z; Bl2[rr0 + 3][r0] = vBl0.w;
            Bl2[rr1 + 0][r1] = vBl1.x; Bl2[rr1 + 1][r1] = vBl1.y;
            Bl2[rr1 + 2][r1] = vBl1.z; Bl2[rr1 + 3][r1] = vBl1.w;
        }
        __syncthreads();

        if (kt + KT < Ec) {
            const int koff = (kt + KT) * 2;
            vAh0 = *(const uint4*)(pAh0 + koff); vAh1 = *(const uint4*)(pAh1 + koff);
            vAl0 = *(const uint4*)(pAl0 + koff); vAl1 = *(const uint4*)(pAl1 + koff);
            vBh0 = *(const uint4*)(pBh0 + koff); vBh1 = *(const uint4*)(pBh1 + koff);
            vBl0 = *(const uint4*)(pBl0 + koff); vBl1 = *(const uint4*)(pBl1 + koff);
        }

        #pragma unroll
        for (int s16 = 0; s16 < 2; s16++) {
            const int kb = s16 * 8;
            uint32_t ah[4][4], al[4][4], bh[4][2], bl[4][2];
            #pragma unroll
            for (int mt = 0; mt < 4; mt++) {
                const int m = mbase + mt * 16 + gid;
                ah[mt][0] = Ah2[kb + tig][m];
                ah[mt][1] = Ah2[kb + tig][m + 8];
                ah[mt][2] = Ah2[kb + tig + 4][m];
                ah[mt][3] = Ah2[kb + tig + 4][m + 8];
                al[mt][0] = Al2[kb + tig][m];
                al[mt][1] = Al2[kb + tig][m + 8];
                al[mt][2] = Al2[kb + tig + 4][m];
                al[mt][3] = Al2[kb + tig + 4][m + 8];
            }
            #pragma unroll
            for (int nt = 0; nt < 4; nt++) {
                const int n = nbase + nt * 8 + gid;
                bh[nt][0] = Bh2[kb + tig][n];
                bh[nt][1] = Bh2[kb + tig + 4][n];
                bl[nt][0] = Bl2[kb + tig][n];
                bl[nt][1] = Bl2[kb + tig + 4][n];
            }
            #pragma unroll
            for (int mt = 0; mt < 4; mt++)
              #pragma unroll
              for (int nt = 0; nt < 4; nt++) {
                  mma_bf16(acc[mt][nt], ah[mt], bh[nt]);
                  mma_bf16(acc[mt][nt], ah[mt], bl[nt]);
                  mma_bf16(acc[mt][nt], al[mt], bh[nt]);
              }
        }
    }

    if (z <= 2) {
        uint32_t *AH, *AL;
        if (z == 0)      { AH = g_qbh; AL = g_qbl; }
        else if (z == 1) { AH = g_kbh; AL = g_kbl; }
        else             { AH = g_vbh; AL = g_vbl; }
        #pragma unroll
        for (int mt = 0; mt < 4; mt++) {
            const int r = m0 + mbase + mt * 16 + gid;
            #pragma unroll
            for (int nt = 0; nt < 4; nt++) {
                const int c = n0 + nbase + nt * 8 + 2 * tig;
                const float bb0 = bias[c], bb1 = bias[c + 1];
                uint32_t hw, lw;
                split2f((acc[mt][nt][0] + bb0) * scale, (acc[mt][nt][1] + bb1) * scale, hw, lw);
                const size_t w0 = ((size_t)r * Ec + c) >> 1;
                AH[w0] = hw; AL[w0] = lw;
                split2f((acc[mt][nt][2] + bb0) * scale, (acc[mt][nt][3] + bb1) * scale, hw, lw);
                const size_t w1 = ((size_t)(r + 8) * Ec + c) >> 1;
                AH[w1] = hw; AL[w1] = lw;
            }
        }
    } else {
        float* outp = (z == 3) ? g_kg : g_vg;
        #pragma unroll
        for (int mt = 0; mt < 4; mt++) {
            const int r = m0 + mbase + mt * 16 + gid;
            #pragma unroll
            for (int nt = 0; nt < 4; nt++) {
                const int c = n0 + nbase + nt * 8 + 2 * tig;
                const float bb0 = bias[c], bb1 = bias[c + 1];
                float2 o0 = make_float2(acc[mt][nt][0] + bb0, acc[mt][nt][1] + bb1);
                float2 o1 = make_float2(acc[mt][nt][2] + bb0, acc[mt][nt][3] + bb1);
                *(float2*)&outp[(size_t)r * Ec + c] = o0;
                *(float2*)&outp[(size_t)(r + 8) * Ec + c] = o1;
            }
        }
    }
}

// ---------------- 1c) transpose V bf16 -> [b][h][d][s] ----------------
__global__ __launch_bounds__(256) void transpose_v()
{
    const int s0 = blockIdx.x * 64;
    const int h  = blockIdx.y, b = blockIdx.z;
    __shared__ unsigned short smh[64][65];
    __shared__ unsigned short sml[64][65];
    const int t = threadIdx.x;
    {
        const int s = t >> 2, dp0 = (t & 3) * 8;
        const size_t off = ((size_t)(b * Sc + s0 + s) * Ec + h * 64) / 2 + dp0;
        #pragma unroll
        for (int u = 0; u < 2; u++) {
            uint4 vh = ((const uint4*)(g_vbh + off))[u];
            uint4 vl = ((const uint4*)(g_vbl + off))[u];
            const int d0 = (dp0 + u * 4) * 2;
            smh[s][d0+0] = (unsigned short)vh.x; smh[s][d0+1] = (unsigned short)(vh.x >> 16);
            smh[s][d0+2] = (unsigned short)vh.y; smh[s][d0+3] = (unsigned short)(vh.y >> 16);
            smh[s][d0+4] = (unsigned short)vh.z; smh[s][d0+5] = (unsigned short)(vh.z >> 16);
            smh[s][d0+6] = (unsigned short)vh.w; smh[s][d0+7] = (unsigned short)(vh.w >> 16);
            sml[s][d0+0] = (unsigned short)vl.x; sml[s][d0+1] = (unsigned short)(vl.x >> 16);
            sml[s][d0+2] = (unsigned short)vl.y; sml[s][d0+3] = (unsigned short)(vl.y >> 16);
            sml[s][d0+4] = (unsigned short)vl.z; sml[s][d0+5] = (unsigned short)(vl.z >> 16);
            sml[s][d0+6] = (unsigned short)vl.w; sml[s][d0+7] = (unsigned short)(vl.w >> 16);
        }
    }
    __syncthreads();
    {
        const int d = t >> 2, sp0 = (t & 3) * 8;
        const size_t off = ((size_t)((b * Hc + h) * HDc + d) * Sc) / 2 + s0 / 2;
        #pragma unroll
        for (int u = 0; u < 8; u++) {
            const int sp = sp0 + u;
            g_vth[off + sp] = (uint32_t)smh[2*sp][d] | ((uint32_t)smh[2*sp+1][d] << 16);
            g_vtl[off + sp] = (uint32_t)sml[2*sp][d] | ((uint32_t)sml[2*sp+1][d] << 16);
        }
    }
}

// ---------------- 2) qg ----------------
__global__ __launch_bounds__(128) void qg_gemm(const float* __restrict__ x,
                                               const float* __restrict__ w,
                                               const float* __restrict__ bias)
{
    const int m  = blockIdx.y;          // 0..63
    const int b  = m >> 5, g = m & 31;
    const int c  = blockIdx.x * 128 + threadIdx.x;
    const float* xr = x + (size_t)(b * Sc + g) * Ec;
    __shared__ float xs[Ec];
    const int t = threadIdx.x;
    #pragma unroll
    for (int i = 0; i < 6; i++) xs[t + 128 * i] = xr[t + 128 * i];
    __syncthreads();
    float acc = 0.0f;
    #pragma unroll 8
    for (int k = 0; k < Ec; k++)
        acc += xs[k] * __ldg(&w[(size_t)k * Ec + c]);
    g_qg[(size_t)m * Ec + c] = (acc + bias[c]) * 0.125f;
}

// ---------------- 3) flash attention on mma (bf16 3-term split) ----------------
// smem word offsets (uint32 units), all arrays [32][72]
#define FO_QH 0
#define FO_QL 2304
#define FO_KH 4608
#define FO_KL 6912
#define FO_VH 9216
#define FO_VL 11520
#define FO_PH 13824
#define FO_PL 16128
#define FO_MB 18432
#define FLASH_SMEM ((18432 + 64) * 4)

__global__ __launch_bounds__(128) void flash_mma(const int* __restrict__ mask,
                                                 float* __restrict__ out)
{
    extern __shared__ uint32_t sm[];
    uint32_t* Qh = sm + FO_QH;  uint32_t* Ql = sm + FO_QL;
    uint32_t* Kh = sm + FO_KH;  uint32_t* Kl = sm + FO_KL;
    uint32_t* Vh = sm + FO_VH;  uint32_t* Vl = sm + FO_VL;
    uint32_t* Ph = sm + FO_PH;  uint32_t* Pl = sm + FO_PL;
    float* maskb = (float*)(sm + FO_MB);

    const int q0 = blockIdx.x * 64;
    const int h  = blockIdx.y;
    const int b  = blockIdx.z;
    const int t    = threadIdx.x;
    const int lane = t & 31;
    const int w    = t >> 5;
    const int gid  = lane >> 2;
    const int tig  = lane & 3;
    const int qb   = w * 16;

    // load Q tile (once)
    {
        const int q = t >> 1, dp0 = (t & 1) * 16;
        const size_t off = ((size_t)(b * Sc + q0 + q) * Ec + h * 64) / 2 + dp0;
        #pragma unroll
        for (int j = 0; j < 4; j++) {
            uint4 vh = ((const uint4*)(g_qbh + off))[j];
            uint4 vl = ((const uint4*)(g_qbl + off))[j];
            const int dp = dp0 + 4 * j;
            Qh[(dp+0)*72 + q] = vh.x; Qh[(dp+1)*72 + q] = vh.y;
            Qh[(dp+2)*72 + q] = vh.z; Qh[(dp+3)*72 + q] = vh.w;
            Ql[(dp+0)*72 + q] = vl.x; Ql[(dp+1)*72 + q] = vl.y;
            Ql[(dp+2)*72 + q] = vl.z; Ql[(dp+3)*72 + q] = vl.w;
        }
    }

    float m0v = NEG_INF, m1v = NEG_INF, l0v = 0.0f, l1v = 0.0f;
    float O[8][4];
    #pragma unroll
    for (int nt = 0; nt < 8; nt++)
      #pragma unroll
      for (int i = 0; i < 4; i++) O[nt][i] = 0.0f;

    const int qi0 = q0 + qb + gid;
    const int qi1 = qi0 + 8;

    for (int tt = 0; tt < 10; tt++) {
        const bool is_sel = (tt == 0);
        const int tstart = is_sel ? 0 : (q0 - Wc + (tt - 1) * 64);
        if (!is_sel && (tstart < 0 || tstart + 64 > Sc)) continue;

        __syncthreads();
        // K loader
        {
            const int s = t >> 1, dp0 = (t & 1) * 16;
            const size_t off = ((size_t)(b * Sc + tstart + s) * Ec + h * 64) / 2 + dp0;
            #pragma unroll
            for (int j = 0; j < 4; j++) {
                uint4 vh = ((const uint4*)(g_kbh + off))[j];
                uint4 vl = ((const uint4*)(g_kbl + off))[j];
                const int dp = dp0 + 4 * j;
                Kh[(dp+0)*72 + s] = vh.x; Kh[(dp+1)*72 + s] = vh.y;
                Kh[(dp+2)*72 + s] = vh.z; Kh[(dp+3)*72 + s] = vh.w;
                Kl[(dp+0)*72 + s] = vl.x; Kl[(dp+1)*72 + s] = vl.y;
                Kl[(dp+2)*72 + s] = vl.z; Kl[(dp+3)*72 + s] = vl.w;
            }
        }
        // V loader (transposed layout)
        {
            const int d = t >> 1, sp0 = (t & 1) * 16;
            const size_t off = ((size_t)((b * Hc + h) * HDc + d) * Sc + tstart) / 2 + sp0;
            #pragma unroll
            for (int j = 0; j < 4; j++) {
                uint4 vh = ((const uint4*)(g_vth + off))[j];
                uint4 vl = ((const uint4*)(g_vtl + off))[j];
                const int sp = sp0 + 4 * j;
                Vh[(sp+0)*72 + d] = vh.x; Vh[(sp+1)*72 + d] = vh.y;
                Vh[(sp+2)*72 + d] = vh.z; Vh[(sp+3)*72 + d] = vh.w;
                Vl[(sp+0)*72 + d] = vl.x; Vl[(sp+1)*72 + d] = vl.y;
                Vl[(sp+2)*72 + d] = vl.z; Vl[(sp+3)*72 + d] = vl.w;
            }
        }
        if (t < 64) {
            if (is_sel) maskb[t] = (t < Gc) ? 0.0f : NEG_INF;
            else maskb[t] = (mask[b * Sc + tstart + t] != 0) ? -10000.0f : 0.0f;
        }
        __syncthreads();

        // ---- QK ----
        float acc[8][4];
        #pragma unroll
        for (int nt = 0; nt < 8; nt++)
          #pragma unroll
          for (int i = 0; i < 4; i++) acc[nt][i] = 0.0f;

        #pragma unroll
        for (int ks = 0; ks < 4; ks++) {
            const int kb = ks * 8;
            uint32_t ah[4], al[4];
            ah[0] = Qh[(kb+tig)*72 + qb+gid];   ah[1] = Qh[(kb+tig)*72 + qb+gid+8];
            ah[2] = Qh[(kb+tig+4)*72 + qb+gid]; ah[3] = Qh[(kb+tig+4)*72 + qb+gid+8];
            al[0] = Ql[(kb+tig)*72 + qb+gid];   al[1] = Ql[(kb+tig)*72 + qb+gid+8];
            al[2] = Ql[(kb+tig+4)*72 + qb+gid]; al[3] = Ql[(kb+tig+4)*72 + qb+gid+8];
            #pragma unroll
            for (int nt = 0; nt < 8; nt++) {
                uint32_t bh[2], bl[2];
                bh[0] = Kh[(kb+tig)*72 + nt*8+gid]; bh[1] = Kh[(kb+tig+4)*72 + nt*8+gid];
                bl[0] = Kl[(kb+tig)*72 + nt*8+gid]; bl[1] = Kl[(kb+tig+4)*72 + nt*8+gid];
                mma_bf16(acc[nt], ah, bh);
                mma_bf16(acc[nt], ah, bl);
                mma_bf16(acc[nt], al, bh);
            }
        }

        // ---- mask + online softmax (per-warp rows, tig-group reductions) ----
        float tm0 = NEG_INF, tm1 = NEG_INF;
        #pragma unroll
        for (int nt = 0; nt < 8; nt++) {
            const int col0 = nt * 8 + 2 * tig, col1 = col0 + 1;
            const float mb0 = maskb[col0], mb1 = maskb[col1];
            if (is_sel) {
                acc[nt][0] += mb0; acc[nt][1] += mb1;
                acc[nt][2] += mb0; acc[nt][3] += mb1;
            } else {
                const int p0 = tstart + col0, p1 = tstart + col1;
                acc[nt][0] = (p0 >= qi0 - Wc && p0 <= qi0 + Wc) ? acc[nt][0] + mb0 : NEG_INF;
                acc[nt][1] = (p1 >= qi0 - Wc && p1 <= qi0 + Wc) ? acc[nt][1] + mb1 : NEG_INF;
                acc[nt][2] = (p0 >= qi1 - Wc && p0 <= qi1 + Wc) ? acc[nt][2] + mb0 : NEG_INF;
                acc[nt][3] = (p1 >= qi1 - Wc && p1 <= qi1 + Wc) ? acc[nt][3] + mb1 : NEG_INF;
            }
            tm0 = fmaxf(tm0, fmaxf(acc[nt][0], acc[nt][1]));
            tm1 = fmaxf(tm1, fmaxf(acc[nt][2], acc[nt][3]));
        }
        tm0 = fmaxf(tm0, __shfl_xor_sync(0xffffffffu, tm0, 1));
        tm0 = fmaxf(tm0, __shfl_xor_sync(0xffffffffu, tm0, 2));
        tm1 = fmaxf(tm1, __shfl_xor_sync(0xffffffffu, tm1, 1));
        tm1 = fmaxf(tm1, __shfl_xor_sync(0xffffffffu, tm1, 2));

        const float mn0 = fmaxf(m0v, tm0), mn1 = fmaxf(m1v, tm1);
        const float a0 = __expf(m0v - mn0), a1 = __expf(m1v - mn1);
        float sum0 = 0.0f, sum1 = 0.0f;
        #pragma unroll
        for (int nt = 0; nt < 8; nt++) {
            const float p00 = __expf(acc[nt][0] - mn0);
            const float p01 = __expf(acc[nt][1] - mn0);
            const float p10 = __expf(acc[nt][2] - mn1);
            const float p11 = __expf(acc[nt][3] - mn1);
            sum0 += p00 + p01; sum1 += p10 + p11;
            uint32_t hw, lw;
            split2f(p00, p01, hw, lw);
            Ph[(nt*4+tig)*72 + qb+gid] = hw;   Pl[(nt*4+tig)*72 + qb+gid] = lw;
            split2f(p10, p11, hw, lw);
            Ph[(nt*4+tig)*72 + qb+gid+8] = hw; Pl[(nt*4+tig)*72 + qb+gid+8] = lw;
        }
        sum0 += __shfl_xor_sync(0xffffffffu, sum0, 1);
        sum0 += __shfl_xor_sync(0xffffffffu, sum0, 2);
        sum1 += __shfl_xor_sync(0xffffffffu, sum1, 1);
        sum1 += __shfl_xor_sync(0xffffffffu, sum1, 2);
        l0v = l0v * a0 + sum0; l1v = l1v * a1 + sum1;
        m0v = mn0; m1v = mn1;
        __syncwarp();

        // ---- rescale O + PV ----
        #pragma unroll
        for (int nt = 0; nt < 8; nt++) {
            O[nt][0] *= a0; O[nt][1] *= a0;
            O[nt][2] *= a1; O[nt][3] *= a1;
        }
        #pragma unroll
        for (int ks = 0; ks < 4; ks++) {
            const int kb = ks * 8;
            uint32_t ah[4], al[4];
            ah[0] = Ph[(kb+tig)*72 + qb+gid];   ah[1] = Ph[(kb+tig)*72 + qb+gid+8];
            ah[2] = Ph[(kb+tig+4)*72 + qb+gid]; ah[3] = Ph[(kb+tig+4)*72 + qb+gid+8];
            al[0] = Pl[(kb+tig)*72 + qb+gid];   al[1] = Pl[(kb+tig)*72 + qb+gid+8];
            al[2] = Pl[(kb+tig+4)*72 + qb+gid]; al[3] = Pl[(kb+tig+4)*72 + qb+gid+8];
            #pragma unroll
            for (int nt = 0; nt < 8; nt++) {
                uint32_t bh[2], bl[2];
                bh[0] = Vh[(kb+tig)*72 + nt*8+gid]; bh[1] = Vh[(kb+tig+4)*72 + nt*8+gid];
                bl[0] = Vl[(kb+tig)*72 + nt*8+gid]; bl[1] = Vl[(kb+tig+4)*72 + nt*8+gid];
                mma_bf16(O[nt], ah, bh);
                mma_bf16(O[nt], ah, bl);
                mma_bf16(O[nt], al, bh);
            }
        }
    }

    // epilogue
    const float li0 = 1.0f / l0v, li1 = 1.0f / l1v;
    #pragma unroll
    for (int nt = 0; nt < 8; nt++) {
        const int c = h * 64 + nt * 8 + 2 * tig;
        float2 o0 = make_float2(O[nt][0] * li0, O[nt][1] * li0);
        float2 o1 = make_float2(O[nt][2] * li1, O[nt][3] * li1);
        *(float2*)&out[(size_t)(b * Sc + qi0) * Ec + c] = o0;
        *(float2*)&out[(size_t)(b * Sc + qi1) * Ec + c] = o1;
    }
}

// ---------------- 4) global scores ----------------
__global__ __launch_bounds__(256) void global_scores()
{
    const int st = blockIdx.x;
    const int h  = blockIdx.y;
    const int b  = blockIdx.z;
    __shared__ float qgs[64 * 32];
    __shared__ float kgs[64 * 128];
    const int t = threadIdx.x;
    {
        const int g = t >> 3, d0 = (t & 7) * 8;
        const float* qp = g_qg + (size_t)(b * Gc + g) * Ec + h * 64 + d0;
        float4 v0 = *(const float4*)qp;
        float4 v1 = *(const float4*)(qp + 4);
        qgs[(d0 + 0) * 32 + g] = v0.x; qgs[(d0 + 1) * 32 + g] = v0.y;
        qgs[(d0 + 2) * 32 + g] = v0.z; qgs[(d0 + 3) * 32 + g] = v0.w;
        qgs[(d0 + 4) * 32 + g] = v1.x; qgs[(d0 + 5) * 32 + g] = v1.y;
        qgs[(d0 + 6) * 32 + g] = v1.z; qgs[(d0 + 7) * 32 + g] = v1.w;
    }
    {
        const int c = t >> 1, d0 = (t & 1) * 32;
        const int p = st * 128 + c;
        const float* kp = g_kg + (size_t)(b * Sc + p) * Ec + h * 64 + d0;
        #pragma unroll
        for (int u = 0; u < 8; u++) {
            float4 v = *(const float4*)(kp + 4 * u);
            kgs[(d0 + 4 * u + 0) * 128 + c] = v.x;
            kgs[(d0 + 4 * u + 1) * 128 + c] = v.y;
            kgs[(d0 + 4 * u + 2) * 128 + c] = v.z;
            kgs[(d0 + 4 * u + 3) * 128 + c] = v.w;
        }
    }
    __syncthreads();
    const int tx = t & 31, ty = t >> 5;
    float s[4][4];
    #pragma unroll
    for (int i = 0; i < 4; i++)
      #pragma unroll
      for (int j = 0; j < 4; j++) s[i][j] = 0.0f;
    #pragma unroll
    for (int d = 0; d < 64; d++) {
        float4 q4 = *(const float4*)&qgs[d * 32 + ty * 4];
        float4 k4 = *(const float4*)&kgs[d * 128 + tx * 4];
        float qa[4] = {q4.x, q4.y, q4.z, q4.w};
        float ka[4] = {k4.x, k4.y, k4.z, k4.w};
        #pragma unroll
        for (int i = 0; i < 4; i++)
          #pragma unroll
          for (int j = 0; j < 4; j++) s[i][j] += qa[i] * ka[j];
    }
    #pragma unroll
    for (int i = 0; i < 4; i++) {
        const int g = ty * 4 + i;
        float* gp = g_gw + (((size_t)(b * Hc + h) * Gc + g) * Sc) + st * 128 + tx * 4;
        *(float4*)gp = make_float4(s[i][0], s[i][1], s[i][2], s[i][3]);
    }
}

// ---------------- 5) row softmax over S for gw ----------------
__global__ __launch_bounds__(256) void global_softmax()
{
    float* p = g_gw + (size_t)blockIdx.x * Sc;
    __shared__ float sm2[8];
    const int t = threadIdx.x, lane = t & 31, wrp = t >> 5;
    float mx = NEG_INF;
    for (int i = t; i < Sc; i += 256) mx = fmaxf(mx, p[i]);
    #pragma unroll
    for (int o = 16; o; o >>= 1) mx = fmaxf(mx, __shfl_xor_sync(0xffffffffu, mx, o));
    if (lane == 0) sm2[wrp] = mx;
    __syncthreads();
    mx = sm2[0];
    #pragma unroll
    for (int i = 1; i < 8; i++) mx = fmaxf(mx, sm2[i]);
    __syncthreads();
    float sum = 0.0f;
    for (int i = t; i < Sc; i += 256) {
        const float e = __expf(p[i] - mx);
        p[i] = e;
        sum += e;
    }
    #pragma unroll
    for (int o = 16; o; o >>= 1) sum += __shfl_xor_sync(0xffffffffu, sum, o);
    if (lane == 0) sm2[wrp] = sum;
    __syncthreads();
    sum = 0.0f;
    #pragma unroll
    for (int i = 0; i < 8; i++) sum += sm2[i];
    const float inv = 1.0f / sum;
    for (int i = t; i < Sc; i += 256) p[i] *= inv;
}

// ---------------- 6) zero gattn accumulator ----------------
__global__ void zero_gattn()
{
    const int idx = blockIdx.x * 256 + threadIdx.x;
    if (idx < Bc * Gc * Ec) g_gattn[idx] = 0.0f;
}

// ---------------- 7) global PV ----------------
__global__ __launch_bounds__(256) void global_pv()
{
    const int sc = blockIdx.x;
    const int h  = blockIdx.y;
    const int b  = blockIdx.z;
    __shared__ float ps[32 * 128];
    const int t  = threadIdx.x;
    const int d  = t & 63;
    const int gq = t >> 6;
    float acc[8];
    #pragma unroll
    for (int gi = 0; gi < 8; gi++) acc[gi] = 0.0f;

    for (int s0 = sc * 512; s0 < sc * 512 + 512; s0 += 128) {
        __syncthreads();
        {
            const int g = t >> 3, sl = (t & 7) * 16;
            const float* src = g_gw + ((size_t)(b * Hc + h) * Gc + g) * Sc + s0 + sl;
            #pragma unroll
            for (int u = 0; u < 4; u++)
                *(float4*)&ps[g * 128 + sl + 4 * u] = *(const float4*)(src + 4 * u);
        }
        __syncthreads();
        for (int sl = 0; sl < 128; sl++) {
            const float vv = g_vg[(size_t)(b * Sc + s0 + sl) * Ec + h * 64 + d];
            #pragma unroll
            for (int gi = 0; gi < 8; gi++)
                acc[gi] += ps[(gq * 8 + gi) * 128 + sl] * vv;
        }
    }
    #pragma unroll
    for (int gi = 0; gi < 8; gi++)
        atomicAdd(&g_gattn[(size_t)(b * Gc + gq * 8 + gi) * Ec + h * 64 + d], acc[gi]);
}

// ---------------- 8) overwrite out[:, :G] with gattn ----------------
__global__ void write_global_rows(float* __restrict__ out)
{
    const int idx = blockIdx.x * 256 + threadIdx.x;
    if (idx < Bc * Gc * Ec) {
        const int e = idx % Ec;
        const int m = idx / Ec;
        const int b = m / Gc, g = m % Gc;
        out[(size_t)(b * Sc + g) * Ec + e] = g_gattn[idx];
    }
}

// ---------------- launch ----------------
extern "C" void kernel_launch(void* const* d_in, const int* in_sizes, int n_in,
                              void* d_out, int out_size)
{
    (void)out_size;
    const float* x    = (const float*)d_in[0];
    const int*   mask = (const int*)d_in[1];
    int wi = 2;
    if (n_in > 2 && in_sizes[2] == 1) wi = 3;
    const float* wq  = (const float*)d_in[wi + 0];
    const float* bq  = (const float*)d_in[wi + 1];
    const float* wk  = (const float*)d_in[wi + 2];
    const float* bk  = (const float*)d_in[wi + 3];
    const float* wv  = (const float*)d_in[wi + 4];
    const float* bv  = (const float*)d_in[wi + 5];
    const float* wqg = (const float*)d_in[wi + 6];
    const float* bqg = (const float*)d_in[wi + 7];
    const float* wkg = (const float*)d_in[wi + 8];
    const float* bkg = (const float*)d_in[wi + 9];
    const float* wvg = (const float*)d_in[wi + 10];
    const float* bvg = (const float*)d_in[wi + 11];
    float* out = (float*)d_out;

    cudaFuncSetAttribute(flash_mma, cudaFuncAttributeMaxDynamicSharedMemorySize, FLASH_SMEM);

    split_x<<<(Mrows * Ec) / 1024, 256>>>(x);
    split_wt<<<dim3(Ec / 32, Ec / 32, 5), 256>>>(wq, wk, wv, wkg, wvg);
    proj_bf16<<<dim3(Ec / 128, Mrows / 128, 5), 256>>>(bq, bk, bv, bkg, bvg);
    transpose_v<<<dim3(Sc / 64, Hc, Bc), 256>>>();
    qg_gemm<<<dim3(Ec / 128, Bc * Gc), 128>>>(x, wqg, bqg);

    flash_mma<<<dim3(Sc / 64, Hc, Bc), 128, FLASH_SMEM>>>(mask, out);

    dim3 gGS(Sc / 128, Hc, Bc);
    global_scores<<<gGS, 256>>>();
    global_softmax<<<Bc * Hc * Gc, 256>>>();
    zero_gattn<<<(Bc * Gc * Ec + 255) / 256, 256>>>();
    dim3 gPV(8, Hc, Bc);
    global_pv<<<gPV, 256>>>();
    write_global_rows<<<(Bc * Gc * Ec + 255) / 256, 256>>>(out);
}

// round 16
// speedup vs baseline: 2.3451x; 1.2053x over previous
#include <cuda_runtime.h>
#include <cuda_bf16.h>
#include <cuda_fp16.h>
#include <stdint.h>

#define NEG_INF (__int_as_float(0xff800000))

#define Bc 2
#define Sc 4096
#define Ec 768
#define Hc 12
#define HDc 64
#define Wc 256
#define Gc 32
#define Mrows (Bc*Sc)   /* 8192 */

// ---------------- scratch (device globals; no allocation allowed) ----------------
__device__ float g_kg[Mrows*Ec];
__device__ float g_vg[Mrows*Ec];
__device__ float g_qg[Bc*Gc*Ec];
__device__ float g_gw[(size_t)Bc*Hc*Gc*Sc];
__device__ float g_gattn[Bc*Gc*Ec];

// fp16 split scratch (uint4 arrays for guaranteed 16B alignment)
__device__ uint4 g_xh4[(size_t)Mrows*Ec/8];              // x hi (fp16)
__device__ uint4 g_wth4[(size_t)6*Ec*Ec/8];              // W^T hi (fp16), 6 mats
__device__ uint4 g_wtl4[(size_t)6*Ec*Ec/8];              // W^T lo (fp16), 6 mats

// q/k/v bf16 hi/lo (packed bf16x2 words, [row][Ec] layout) for flash
__device__ __align__(16) uint32_t g_qbh[(size_t)Mrows*Ec/2];
__device__ __align__(16) uint32_t g_qbl[(size_t)Mrows*Ec/2];
__device__ __align__(16) uint32_t g_kbh[(size_t)Mrows*Ec/2];
__device__ __align__(16) uint32_t g_kbl[(size_t)Mrows*Ec/2];
__device__ __align__(16) uint32_t g_vbh[(size_t)Mrows*Ec/2];
__device__ __align__(16) uint32_t g_vbl[(size_t)Mrows*Ec/2];
// V transposed: [b][h][d=64][s=Sc] bf16, s-pairs packed
__device__ __align__(16) uint32_t g_vth[(size_t)Bc*Hc*HDc*Sc/2];
__device__ __align__(16) uint32_t g_vtl[(size_t)Bc*Hc*HDc*Sc/2];

// ---------------- mma helpers (legacy mma.sync, valid on compute_103) ----------------
__device__ __forceinline__ void mma_bf16(float* d, const uint32_t* a, const uint32_t* b) {
    asm volatile(
        "mma.sync.aligned.m16n8k16.row.col.f32.bf16.bf16.f32 "
        "{%0,%1,%2,%3},{%4,%5,%6,%7},{%8,%9},{%0,%1,%2,%3};"
        : "+f"(d[0]), "+f"(d[1]), "+f"(d[2]), "+f"(d[3])
        : "r"(a[0]), "r"(a[1]), "r"(a[2]), "r"(a[3]), "r"(b[0]), "r"(b[1]));
}

__device__ __forceinline__ void mma_fp16(float* d, const uint32_t* a, const uint32_t* b) {
    asm volatile(
        "mma.sync.aligned.m16n8k16.row.col.f32.f16.f16.f32 "
        "{%0,%1,%2,%3},{%4,%5,%6,%7},{%8,%9},{%0,%1,%2,%3};"
        : "+f"(d[0]), "+f"(d[1]), "+f"(d[2]), "+f"(d[3])
        : "r"(a[0]), "r"(a[1]), "r"(a[2]), "r"(a[3]), "r"(b[0]), "r"(b[1]));
}

__device__ __forceinline__ void split2f(float a, float b, uint32_t& hw, uint32_t& lw) {
    const __nv_bfloat16 ha = __float2bfloat16_rn(a);
    const __nv_bfloat16 hb = __float2bfloat16_rn(b);
    const __nv_bfloat16 la = __float2bfloat16_rn(a - __bfloat162float(ha));
    const __nv_bfloat16 lb = __float2bfloat16_rn(b - __bfloat162float(hb));
    hw = ((uint32_t)*(const unsigned short*)&hb << 16) | *(const unsigned short*)&ha;
    lw = ((uint32_t)*(const unsigned short*)&lb << 16) | *(const unsigned short*)&la;
}

// ---------------- 0a) x -> fp16 hi ----------------
__global__ __launch_bounds__(256) void split_x(const float* __restrict__ x)
{
    const int i = (blockIdx.x * 256 + threadIdx.x) * 4;
    float4 v = *(const float4*)&x[i];
    __half2* ph = (__half2*)g_xh4;
    ph[i/2]     = __floats2half2_rn(v.x, v.y);
    ph[i/2 + 1] = __floats2half2_rn(v.z, v.w);
}

// ---------------- 0b) transpose + split W -> wT[n][k] fp16 hi/lo (6 mats) ----------------
__global__ __launch_bounds__(256) void split_wt(
    const float* __restrict__ w0, const float* __restrict__ w1,
    const float* __restrict__ w2, const float* __restrict__ w3,
    const float* __restrict__ w4, const float* __restrict__ w5)
{
    const int z = blockIdx.z;
    const float* W;
    switch (z) {
      case 0: W = w0; break; case 1: W = w1; break; case 2: W = w2; break;
      case 3: W = w3; break; case 4: W = w4; break; default: W = w5; break;
    }
    __shared__ float tile[32][33];
    const int k0 = blockIdx.x * 32;
    const int n0 = blockIdx.y * 32;
    const int t = threadIdx.x;
    const int tx = t & 31, ty = t >> 5;
    #pragma unroll
    for (int i = 0; i < 4; i++)
        tile[ty + 8*i][tx] = W[(size_t)(k0 + ty + 8*i) * Ec + n0 + tx];
    __syncthreads();
    __half* oh = (__half*)g_wth4 + (size_t)z * Ec * Ec;
    __half* ol = (__half*)g_wtl4 + (size_t)z * Ec * Ec;
    #pragma unroll
    for (int i = 0; i < 4; i++) {
        const float v = tile[tx][ty + 8*i];
        const __half h = __float2half_rn(v);
        const __half l = __float2half_rn(v - __half2float(h));
        oh[(size_t)(n0 + ty + 8*i) * Ec + k0 + tx] = h;
        ol[(size_t)(n0 + ty + 8*i) * Ec + k0 + tx] = l;
    }
}

// ---------------- 1) projection GEMMs: fp16 2-term (xh*(wh+wl)) ----------------
#define SSTR2 136
#define KT 32

__global__ __launch_bounds__(256) void proj_mma(
    const float* __restrict__ b0, const float* __restrict__ b1,
    const float* __restrict__ b2, const float* __restrict__ b3,
    const float* __restrict__ b4)
{
    const int z  = blockIdx.z;
    const float* bias; float scale = 1.0f;
    switch (z) {
      case 0: bias = b0; scale = 0.125f; break;
      case 1: bias = b1; break;
      case 2: bias = b2; break;
      case 3: bias = b3; break;
      default:bias = b4; break;
    }
    const int m0 = blockIdx.y * 128;
    const int n0 = blockIdx.x * 128;

    const char* Axh = (const char*)g_xh4;
    const char* Bwh = (const char*)g_wth4 + (size_t)z * Ec * Ec * 2;
    const char* Bwl = (const char*)g_wtl4 + (size_t)z * Ec * Ec * 2;

    __shared__ uint32_t Ah2[16][SSTR2];
    __shared__ uint32_t Bh2[16][SSTR2];
    __shared__ uint32_t Bl2[16][SSTR2];

    const int t    = threadIdx.x;
    const int lane = t & 31;
    const int warp = t >> 5;
    const int gid  = lane >> 2;
    const int tig  = lane & 3;
    const int mbase = (warp & 1) * 64;
    const int nbase = (warp >> 1) * 32;

    const int r0 = t >> 2,        kq0 = t & 3;
    const int r1 = (t + 256) >> 2, kq1 = (t + 256) & 3;

    const char* pAh0 = Axh + ((size_t)(m0 + r0) * Ec + kq0 * 8) * 2;
    const char* pAh1 = Axh + ((size_t)(m0 + r1) * Ec + kq1 * 8) * 2;
    const char* pBh0 = Bwh + ((size_t)(n0 + r0) * Ec + kq0 * 8) * 2;
    const char* pBh1 = Bwh + ((size_t)(n0 + r1) * Ec + kq1 * 8) * 2;
    const char* pBl0 = Bwl + ((size_t)(n0 + r0) * Ec + kq0 * 8) * 2;
    const char* pBl1 = Bwl + ((size_t)(n0 + r1) * Ec + kq1 * 8) * 2;

    float acc[4][4][4];
    #pragma unroll
    for (int mt = 0; mt < 4; mt++)
      #pragma unroll
      for (int nt = 0; nt < 4; nt++)
        #pragma unroll
        for (int i = 0; i < 4; i++) acc[mt][nt][i] = 0.0f;

    uint4 vAh0 = *(const uint4*)pAh0, vAh1 = *(const uint4*)pAh1;
    uint4 vBh0 = *(const uint4*)pBh0, vBh1 = *(const uint4*)pBh1;
    uint4 vBl0 = *(const uint4*)pBl0, vBl1 = *(const uint4*)pBl1;

    for (int kt = 0; kt < Ec; kt += KT) {
        __syncthreads();
        {
            const int rr0 = kq0 * 4, rr1 = kq1 * 4;
            Ah2[rr0 + 0][r0] = vAh0.x; Ah2[rr0 + 1][r0] = vAh0.y;
            Ah2[rr0 + 2][r0] = vAh0.z; Ah2[rr0 + 3][r0] = vAh0.w;
            Ah2[rr1 + 0][r1] = vAh1.x; Ah2[rr1 + 1][r1] = vAh1.y;
            Ah2[rr1 + 2][r1] = vAh1.z; Ah2[rr1 + 3][r1] = vAh1.w;
            Bh2[rr0 + 0][r0] = vBh0.x; Bh2[rr0 + 1][r0] = vBh0.y;
            Bh2[rr0 + 2][r0] = vBh0.z; Bh2[rr0 + 3][r0] = vBh0.w;
            Bh2[rr1 + 0][r1] = vBh1.x; Bh2[rr1 + 1][r1] = vBh1.y;
            Bh2[rr1 + 2][r1] = vBh1.z; Bh2[rr1 + 3][r1] = vBh1.w;
            Bl2[rr0 + 0][r0] = vBl0.x; Bl2[rr0 + 1][r0] = vBl0.y;
            Bl2[rr0 + 2][r0] = vBl0.z; Bl2[rr0 + 3][r0] = vBl0.w;
            Bl2[rr1 + 0][r1] = vBl1.x; Bl2[rr1 + 1][r1] = vBl1.y;
            Bl2[rr1 + 2][r1] = vBl1.z; Bl2[rr1 + 3][r1] = vBl1.w;
        }
        __syncthreads();

        if (kt + KT < Ec) {
            const int koff = (kt + KT) * 2;
            vAh0 = *(const uint4*)(pAh0 + koff); vAh1 = *(const uint4*)(pAh1 + koff);
            vBh0 = *(const uint4*)(pBh0 + koff); vBh1 = *(const uint4*)(pBh1 + koff);
            vBl0 = *(const uint4*)(pBl0 + koff); vBl1 = *(const uint4*)(pBl1 + koff);
        }

        #pragma unroll
        for (int s16 = 0; s16 < 2; s16++) {
            const int kb = s16 * 8;
            uint32_t ah[4][4], bh[4][2], bl[4][2];
            #pragma unroll
            for (int mt = 0; mt < 4; mt++) {
                const int m = mbase + mt * 16 + gid;
                ah[mt][0] = Ah2[kb + tig][m];
                ah[mt][1] = Ah2[kb + tig][m + 8];
                ah[mt][2] = Ah2[kb + tig + 4][m];
                ah[mt][3] = Ah2[kb + tig + 4][m + 8];
            }
            #pragma unroll
            for (int nt = 0; nt < 4; nt++) {
                const int n = nbase + nt * 8 + gid;
                bh[nt][0] = Bh2[kb + tig][n];
                bh[nt][1] = Bh2[kb + tig + 4][n];
                bl[nt][0] = Bl2[kb + tig][n];
                bl[nt][1] = Bl2[kb + tig + 4][n];
            }
            #pragma unroll
            for (int mt = 0; mt < 4; mt++)
              #pragma unroll
              for (int nt = 0; nt < 4; nt++) {
                  mma_fp16(acc[mt][nt], ah[mt], bh[nt]);
                  mma_fp16(acc[mt][nt], ah[mt], bl[nt]);
              }
        }
    }

    if (z <= 2) {
        uint32_t *AH, *AL;
        if (z == 0)      { AH = g_qbh; AL = g_qbl; }
        else if (z == 1) { AH = g_kbh; AL = g_kbl; }
        else             { AH = g_vbh; AL = g_vbl; }
        #pragma unroll
        for (int mt = 0; mt < 4; mt++) {
            const int r = m0 + mbase + mt * 16 + gid;
            #pragma unroll
            for (int nt = 0; nt < 4; nt++) {
                const int c = n0 + nbase + nt * 8 + 2 * tig;
                const float bb0 = bias[c], bb1 = bias[c + 1];
                uint32_t hw, lw;
                split2f((acc[mt][nt][0] + bb0) * scale, (acc[mt][nt][1] + bb1) * scale, hw, lw);
                const size_t w0 = ((size_t)r * Ec + c) >> 1;
                AH[w0] = hw; AL[w0] = lw;
                split2f((acc[mt][nt][2] + bb0) * scale, (acc[mt][nt][3] + bb1) * scale, hw, lw);
                const size_t w1 = ((size_t)(r + 8) * Ec + c) >> 1;
                AH[w1] = hw; AL[w1] = lw;
            }
        }
    } else {
        float* outp = (z == 3) ? g_kg : g_vg;
        #pragma unroll
        for (int mt = 0; mt < 4; mt++) {
            const int r = m0 + mbase + mt * 16 + gid;
            #pragma unroll
            for (int nt = 0; nt < 4; nt++) {
                const int c = n0 + nbase + nt * 8 + 2 * tig;
                const float bb0 = bias[c], bb1 = bias[c + 1];
                float2 o0 = make_float2(acc[mt][nt][0] + bb0, acc[mt][nt][1] + bb1);
                float2 o1 = make_float2(acc[mt][nt][2] + bb0, acc[mt][nt][3] + bb1);
                *(float2*)&outp[(size_t)r * Ec + c] = o0;
                *(float2*)&outp[(size_t)(r + 8) * Ec + c] = o1;
            }
        }
    }
}

// ---------------- 1b) qg via mma: 64 gathered rows x 128 cols per CTA ----------------
__global__ __launch_bounds__(256) void qg_mma(const float* __restrict__ bias)
{
    const int n0 = blockIdx.x * 128;
    const char* Axh = (const char*)g_xh4;
    const char* Bwh = (const char*)g_wth4 + (size_t)5 * Ec * Ec * 2;
    const char* Bwl = (const char*)g_wtl4 + (size_t)5 * Ec * Ec * 2;

    __shared__ uint32_t Ah2[16][SSTR2];   // cols 0..63 used
    __shared__ uint32_t Bh2[16][SSTR2];
    __shared__ uint32_t Bl2[16][SSTR2];

    const int t    = threadIdx.x;
    const int lane = t & 31;
    const int warp = t >> 5;
    const int gid  = lane >> 2;
    const int tig  = lane & 3;
    const int mbase = (warp & 1) * 32;
    const int nbase = (warp >> 1) * 32;

    // A: one slot per thread: row ra (0..63), kq
    const int ra  = t >> 2, kqa = t & 3;
    const int xrow = (ra >> 5) * Sc + (ra & 31);
    const char* pA = Axh + ((size_t)xrow * Ec + kqa * 8) * 2;
    // B: two slots
    const int r0 = t >> 2,        kq0 = t & 3;
    const int r1 = (t + 256) >> 2, kq1 = (t + 256) & 3;
    const char* pBh0 = Bwh + ((size_t)(n0 + r0) * Ec + kq0 * 8) * 2;
    const char* pBh1 = Bwh + ((size_t)(n0 + r1) * Ec + kq1 * 8) * 2;
    const char* pBl0 = Bwl + ((size_t)(n0 + r0) * Ec + kq0 * 8) * 2;
    const char* pBl1 = Bwl + ((size_t)(n0 + r1) * Ec + kq1 * 8) * 2;

    float acc[2][4][4];
    #pragma unroll
    for (int mt = 0; mt < 2; mt++)
      #pragma unroll
      for (int nt = 0; nt < 4; nt++)
        #pragma unroll
        for (int i = 0; i < 4; i++) acc[mt][nt][i] = 0.0f;

    for (int kt = 0; kt < Ec; kt += KT) {
        const int koff = kt * 2;
        uint4 vA  = *(const uint4*)(pA + koff);
        uint4 vB0 = *(const uint4*)(pBh0 + koff);
        uint4 vB1 = *(const uint4*)(pBh1 + koff);
        uint4 vC0 = *(const uint4*)(pBl0 + koff);
        uint4 vC1 = *(const uint4*)(pBl1 + koff);
        __syncthreads();
        {
            const int rrA = kqa * 4, rr0 = kq0 * 4, rr1 = kq1 * 4;
            Ah2[rrA + 0][ra] = vA.x; Ah2[rrA + 1][ra] = vA.y;
            Ah2[rrA + 2][ra] = vA.z; Ah2[rrA + 3][ra] = vA.w;
            Bh2[rr0 + 0][r0] = vB0.x; Bh2[rr0 + 1][r0] = vB0.y;
            Bh2[rr0 + 2][r0] = vB0.z; Bh2[rr0 + 3][r0] = vB0.w;
            Bh2[rr1 + 0][r1] = vB1.x; Bh2[rr1 + 1][r1] = vB1.y;
            Bh2[rr1 + 2][r1] = vB1.z; Bh2[rr1 + 3][r1] = vB1.w;
            Bl2[rr0 + 0][r0] = vC0.x; Bl2[rr0 + 1][r0] = vC0.y;
            Bl2[rr0 + 2][r0] = vC0.z; Bl2[rr0 + 3][r0] = vC0.w;
            Bl2[rr1 + 0][r1] = vC1.x; Bl2[rr1 + 1][r1] = vC1.y;
            Bl2[rr1 + 2][r1] = vC1.z; Bl2[rr1 + 3][r1] = vC1.w;
        }
        __syncthreads();

        #pragma unroll
        for (int s16 = 0; s16 < 2; s16++) {
            const int kb = s16 * 8;
            uint32_t ah[2][4], bh[4][2], bl[4][2];
            #pragma unroll
            for (int mt = 0; mt < 2; mt++) {
                const int m = mbase + mt * 16 + gid;
                ah[mt][0] = Ah2[kb + tig][m];
                ah[mt][1] = Ah2[kb + tig][m + 8];
                ah[mt][2] = Ah2[kb + tig + 4][m];
                ah[mt][3] = Ah2[kb + tig + 4][m + 8];
            }
            #pragma unroll
            for (int nt = 0; nt < 4; nt++) {
                const int n = nbase + nt * 8 + gid;
                bh[nt][0] = Bh2[kb + tig][n];
                bh[nt][1] = Bh2[kb + tig + 4][n];
                bl[nt][0] = Bl2[kb + tig][n];
                bl[nt][1] = Bl2[kb + tig + 4][n];
            }
            #pragma unroll
            for (int mt = 0; mt < 2; mt++)
              #pragma unroll
              for (int nt = 0; nt < 4; nt++) {
                  mma_fp16(acc[mt][nt], ah[mt], bh[nt]);
                  mma_fp16(acc[mt][nt], ah[mt], bl[nt]);
              }
        }
    }

    #pragma unroll
    for (int mt = 0; mt < 2; mt++) {
        const int r = mbase + mt * 16 + gid;   // qg row 0..63
        #pragma unroll
        for (int nt = 0; nt < 4; nt++) {
            const int c = n0 + nbase + nt * 8 + 2 * tig;
            const float bb0 = bias[c], bb1 = bias[c + 1];
            float2 o0 = make_float2((acc[mt][nt][0] + bb0) * 0.125f,
                                    (acc[mt][nt][1] + bb1) * 0.125f);
            float2 o1 = make_float2((acc[mt][nt][2] + bb0) * 0.125f,
                                    (acc[mt][nt][3] + bb1) * 0.125f);
            *(float2*)&g_qg[(size_t)r * Ec + c] = o0;
            *(float2*)&g_qg[(size_t)(r + 8) * Ec + c] = o1;
        }
    }
}

// ---------------- 1c) transpose V bf16 -> [b][h][d][s] ----------------
__global__ __launch_bounds__(256) void transpose_v()
{
    const int s0 = blockIdx.x * 64;
    const int h  = blockIdx.y, b = blockIdx.z;
    __shared__ unsigned short smh[64][65];
    __shared__ unsigned short sml[64][65];
    const int t = threadIdx.x;
    {
        const int s = t >> 2, dp0 = (t & 3) * 8;
        const size_t off = ((size_t)(b * Sc + s0 + s) * Ec + h * 64) / 2 + dp0;
        #pragma unroll
        for (int u = 0; u < 2; u++) {
            uint4 vh = ((const uint4*)(g_vbh + off))[u];
            uint4 vl = ((const uint4*)(g_vbl + off))[u];
            const int d0 = (dp0 + u * 4) * 2;
            smh[s][d0+0] = (unsigned short)vh.x; smh[s][d0+1] = (unsigned short)(vh.x >> 16);
            smh[s][d0+2] = (unsigned short)vh.y; smh[s][d0+3] = (unsigned short)(vh.y >> 16);
            smh[s][d0+4] = (unsigned short)vh.z; smh[s][d0+5] = (unsigned short)(vh.z >> 16);
            smh[s][d0+6] = (unsigned short)vh.w; smh[s][d0+7] = (unsigned short)(vh.w >> 16);
            sml[s][d0+0] = (unsigned short)vl.x; sml[s][d0+1] = (unsigned short)(vl.x >> 16);
            sml[s][d0+2] = (unsigned short)vl.y; sml[s][d0+3] = (unsigned short)(vl.y >> 16);
            sml[s][d0+4] = (unsigned short)vl.z; sml[s][d0+5] = (unsigned short)(vl.z >> 16);
            sml[s][d0+6] = (unsigned short)vl.w; sml[s][d0+7] = (unsigned short)(vl.w >> 16);
        }
    }
    __syncthreads();
    {
        const int d = t >> 2, sp0 = (t & 3) * 8;
        const size_t off = ((size_t)((b * Hc + h) * HDc + d) * Sc) / 2 + s0 / 2;
        #pragma unroll
        for (int u = 0; u < 8; u++) {
            const int sp = sp0 + u;
            g_vth[off + sp] = (uint32_t)smh[2*sp][d] | ((uint32_t)smh[2*sp+1][d] << 16);
            g_vtl[off + sp] = (uint32_t)sml[2*sp][d] | ((uint32_t)sml[2*sp+1][d] << 16);
        }
    }
}

// ---------------- 3) flash attention on mma (bf16 3-term split) ----------------
#define FO_QH 0
#define FO_QL 2304
#define FO_KH 4608
#define FO_KL 6912
#define FO_VH 9216
#define FO_VL 11520
#define FO_PH 13824
#define FO_PL 16128
#define FO_MB 18432
#define FLASH_SMEM ((18432 + 64) * 4)

__global__ __launch_bounds__(128) void flash_mma(const int* __restrict__ mask,
                                                 float* __restrict__ out)
{
    extern __shared__ uint32_t sm[];
    uint32_t* Qh = sm + FO_QH;  uint32_t* Ql = sm + FO_QL;
    uint32_t* Kh = sm + FO_KH;  uint32_t* Kl = sm + FO_KL;
    uint32_t* Vh = sm + FO_VH;  uint32_t* Vl = sm + FO_VL;
    uint32_t* Ph = sm + FO_PH;  uint32_t* Pl = sm + FO_PL;
    float* maskb = (float*)(sm + FO_MB);

    const int q0 = blockIdx.x * 64;
    const int h  = blockIdx.y;
    const int b  = blockIdx.z;
    const int t    = threadIdx.x;
    const int lane = t & 31;
    const int w    = t >> 5;
    const int gid  = lane >> 2;
    const int tig  = lane & 3;
    const int qb   = w * 16;

    {
        const int q = t >> 1, dp0 = (t & 1) * 16;
        const size_t off = ((size_t)(b * Sc + q0 + q) * Ec + h * 64) / 2 + dp0;
        #pragma unroll
        for (int j = 0; j < 4; j++) {
            uint4 vh = ((const uint4*)(g_qbh + off))[j];
            uint4 vl = ((const uint4*)(g_qbl + off))[j];
            const int dp = dp0 + 4 * j;
            Qh[(dp+0)*72 + q] = vh.x; Qh[(dp+1)*72 + q] = vh.y;
            Qh[(dp+2)*72 + q] = vh.z; Qh[(dp+3)*72 + q] = vh.w;
            Ql[(dp+0)*72 + q] = vl.x; Ql[(dp+1)*72 + q] = vl.y;
            Ql[(dp+2)*72 + q] = vl.z; Ql[(dp+3)*72 + q] = vl.w;
        }
    }

    float m0v = NEG_INF, m1v = NEG_INF, l0v = 0.0f, l1v = 0.0f;
    float O[8][4];
    #pragma unroll
    for (int nt = 0; nt < 8; nt++)
      #pragma unroll
      for (int i = 0; i < 4; i++) O[nt][i] = 0.0f;

    const int qi0 = q0 + qb + gid;
    const int qi1 = qi0 + 8;

    for (int tt = 0; tt < 10; tt++) {
        const bool is_sel = (tt == 0);
        const int tstart = is_sel ? 0 : (q0 - Wc + (tt - 1) * 64);
        if (!is_sel && (tstart < 0 || tstart + 64 > Sc)) continue;

        __syncthreads();
        {
            const int s = t >> 1, dp0 = (t & 1) * 16;
            const size_t off = ((size_t)(b * Sc + tstart + s) * Ec + h * 64) / 2 + dp0;
            #pragma unroll
            for (int j = 0; j < 4; j++) {
                uint4 vh = ((const uint4*)(g_kbh + off))[j];
                uint4 vl = ((const uint4*)(g_kbl + off))[j];
                const int dp = dp0 + 4 * j;
                Kh[(dp+0)*72 + s] = vh.x; Kh[(dp+1)*72 + s] = vh.y;
                Kh[(dp+2)*72 + s] = vh.z; Kh[(dp+3)*72 + s] = vh.w;
                Kl[(dp+0)*72 + s] = vl.x; Kl[(dp+1)*72 + s] = vl.y;
                Kl[(dp+2)*72 + s] = vl.z; Kl[(dp+3)*72 + s] = vl.w;
            }
        }
        {
            const int d = t >> 1, sp0 = (t & 1) * 16;
            const size_t off = ((size_t)((b * Hc + h) * HDc + d) * Sc + tstart) / 2 + sp0;
            #pragma unroll
            for (int j = 0; j < 4; j++) {
                uint4 vh = ((const uint4*)(g_vth + off))[j];
                uint4 vl = ((const uint4*)(g_vtl + off))[j];
                const int sp = sp0 + 4 * j;
                Vh[(sp+0)*72 + d] = vh.x; Vh[(sp+1)*72 + d] = vh.y;
                Vh[(sp+2)*72 + d] = vh.z; Vh[(sp+3)*72 + d] = vh.w;
                Vl[(sp+0)*72 + d] = vl.x; Vl[(sp+1)*72 + d] = vl.y;
                Vl[(sp+2)*72 + d] = vl.z; Vl[(sp+3)*72 + d] = vl.w;
            }
        }
        if (t < 64) {
            if (is_sel) maskb[t] = (t < Gc) ? 0.0f : NEG_INF;
            else maskb[t] = (mask[b * Sc + tstart + t] != 0) ? -10000.0f : 0.0f;
        }
        __syncthreads();

        float acc[8][4];
        #pragma unroll
        for (int nt = 0; nt < 8; nt++)
          #pragma unroll
          for (int i = 0; i < 4; i++) acc[nt][i] = 0.0f;

        #pragma unroll
        for (int ks = 0; ks < 4; ks++) {
            const int kb = ks * 8;
            uint32_t ah[4], al[4];
            ah[0] = Qh[(kb+tig)*72 + qb+gid];   ah[1] = Qh[(kb+tig)*72 + qb+gid+8];
            ah[2] = Qh[(kb+tig+4)*72 + qb+gid]; ah[3] = Qh[(kb+tig+4)*72 + qb+gid+8];
            al[0] = Ql[(kb+tig)*72 + qb+gid];   al[1] = Ql[(kb+tig)*72 + qb+gid+8];
            al[2] = Ql[(kb+tig+4)*72 + qb+gid]; al[3] = Ql[(kb+tig+4)*72 + qb+gid+8];
            #pragma unroll
            for (int nt = 0; nt < 8; nt++) {
                uint32_t bh[2], bl[2];
                bh[0] = Kh[(kb+tig)*72 + nt*8+gid]; bh[1] = Kh[(kb+tig+4)*72 + nt*8+gid];
                bl[0] = Kl[(kb+tig)*72 + nt*8+gid]; bl[1] = Kl[(kb+tig+4)*72 + nt*8+gid];
                mma_bf16(acc[nt], ah, bh);
                mma_bf16(acc[nt], ah, bl);
                mma_bf16(acc[nt], al, bh);
            }
        }

        float tm0 = NEG_INF, tm1 = NEG_INF;
        #pragma unroll
        for (int nt = 0; nt < 8; nt++) {
            const int col0 = nt * 8 + 2 * tig, col1 = col0 + 1;
            const float mb0 = maskb[col0], mb1 = maskb[col1];
            if (is_sel) {
                acc[nt][0] += mb0; acc[nt][1] += mb1;
                acc[nt][2] += mb0; acc[nt][3] += mb1;
            } else {
                const int p0 = tstart + col0, p1 = tstart + col1;
                acc[nt][0] = (p0 >= qi0 - Wc && p0 <= qi0 + Wc) ? acc[nt][0] + mb0 : NEG_INF;
                acc[nt][1] = (p1 >= qi0 - Wc && p1 <= qi0 + Wc) ? acc[nt][1] + mb1 : NEG_INF;
                acc[nt][2] = (p0 >= qi1 - Wc && p0 <= qi1 + Wc) ? acc[nt][2] + mb0 : NEG_INF;
                acc[nt][3] = (p1 >= qi1 - Wc && p1 <= qi1 + Wc) ? acc[nt][3] + mb1 : NEG_INF;
            }
            tm0 = fmaxf(tm0, fmaxf(acc[nt][0], acc[nt][1]));
            tm1 = fmaxf(tm1, fmaxf(acc[nt][2], acc[nt][3]));
        }
        tm0 = fmaxf(tm0, __shfl_xor_sync(0xffffffffu, tm0, 1));
        tm0 = fmaxf(tm0, __shfl_xor_sync(0xffffffffu, tm0, 2));
        tm1 = fmaxf(tm1, __shfl_xor_sync(0xffffffffu, tm1, 1));
        tm1 = fmaxf(tm1, __shfl_xor_sync(0xffffffffu, tm1, 2));

        const float mn0 = fmaxf(m0v, tm0), mn1 = fmaxf(m1v, tm1);
        const float a0 = __expf(m0v - mn0), a1 = __expf(m1v - mn1);
        float sum0 = 0.0f, sum1 = 0.0f;
        #pragma unroll
        for (int nt = 0; nt < 8; nt++) {
            const float p00 = __expf(acc[nt][0] - mn0);
            const float p01 = __expf(acc[nt][1] - mn0);
            const float p10 = __expf(acc[nt][2] - mn1);
            const float p11 = __expf(acc[nt][3] - mn1);
            sum0 += p00 + p01; sum1 += p10 + p11;
            uint32_t hw, lw;
            split2f(p00, p01, hw, lw);
            Ph[(nt*4+tig)*72 + qb+gid] = hw;   Pl[(nt*4+tig)*72 + qb+gid] = lw;
            split2f(p10, p11, hw, lw);
            Ph[(nt*4+tig)*72 + qb+gid+8] = hw; Pl[(nt*4+tig)*72 + qb+gid+8] = lw;
        }
        sum0 += __shfl_xor_sync(0xffffffffu, sum0, 1);
        sum0 += __shfl_xor_sync(0xffffffffu, sum0, 2);
        sum1 += __shfl_xor_sync(0xffffffffu, sum1, 1);
        sum1 += __shfl_xor_sync(0xffffffffu, sum1, 2);
        l0v = l0v * a0 + sum0; l1v = l1v * a1 + sum1;
        m0v = mn0; m1v = mn1;
        __syncwarp();

        #pragma unroll
        for (int nt = 0; nt < 8; nt++) {
            O[nt][0] *= a0; O[nt][1] *= a0;
            O[nt][2] *= a1; O[nt][3] *= a1;
        }
        #pragma unroll
        for (int ks = 0; ks < 4; ks++) {
            const int kb = ks * 8;
            uint32_t ah[4], al[4];
            ah[0] = Ph[(kb+tig)*72 + qb+gid];   ah[1] = Ph[(kb+tig)*72 + qb+gid+8];
            ah[2] = Ph[(kb+tig+4)*72 + qb+gid]; ah[3] = Ph[(kb+tig+4)*72 + qb+gid+8];
            al[0] = Pl[(kb+tig)*72 + qb+gid];   al[1] = Pl[(kb+tig)*72 + qb+gid+8];
            al[2] = Pl[(kb+tig+4)*72 + qb+gid]; al[3] = Pl[(kb+tig+4)*72 + qb+gid+8];
            #pragma unroll
            for (int nt = 0; nt < 8; nt++) {
                uint32_t bh[2], bl[2];
                bh[0] = Vh[(kb+tig)*72 + nt*8+gid]; bh[1] = Vh[(kb+tig+4)*72 + nt*8+gid];
                bl[0] = Vl[(kb+tig)*72 + nt*8+gid]; bl[1] = Vl[(kb+tig+4)*72 + nt*8+gid];
                mma_bf16(O[nt], ah, bh);
                mma_bf16(O[nt], ah, bl);
                mma_bf16(O[nt], al, bh);
            }
        }
    }

    const float li0 = 1.0f / l0v, li1 = 1.0f / l1v;
    #pragma unroll
    for (int nt = 0; nt < 8; nt++) {
        const int c = h * 64 + nt * 8 + 2 * tig;
        float2 o0 = make_float2(O[nt][0] * li0, O[nt][1] * li0);
        float2 o1 = make_float2(O[nt][2] * li1, O[nt][3] * li1);
        *(float2*)&out[(size_t)(b * Sc + qi0) * Ec + c] = o0;
        *(float2*)&out[(size_t)(b * Sc + qi1) * Ec + c] = o1;
    }
}

// ---------------- 4) global scores ----------------
__global__ __launch_bounds__(256) void global_scores()
{
    const int st = blockIdx.x;
    const int h  = blockIdx.y;
    const int b  = blockIdx.z;
    __shared__ float qgs[64 * 32];
    __shared__ float kgs[64 * 128];
    const int t = threadIdx.x;
    {
        const int g = t >> 3, d0 = (t & 7) * 8;
        const float* qp = g_qg + (size_t)(b * Gc + g) * Ec + h * 64 + d0;
        float4 v0 = *(const float4*)qp;
        float4 v1 = *(const float4*)(qp + 4);
        qgs[(d0 + 0) * 32 + g] = v0.x; qgs[(d0 + 1) * 32 + g] = v0.y;
        qgs[(d0 + 2) * 32 + g] = v0.z; qgs[(d0 + 3) * 32 + g] = v0.w;
        qgs[(d0 + 4) * 32 + g] = v1.x; qgs[(d0 + 5) * 32 + g] = v1.y;
        qgs[(d0 + 6) * 32 + g] = v1.z; qgs[(d0 + 7) * 32 + g] = v1.w;
    }
    {
        const int c = t >> 1, d0 = (t & 1) * 32;
        const int p = st * 128 + c;
        const float* kp = g_kg + (size_t)(b * Sc + p) * Ec + h * 64 + d0;
        #pragma unroll
        for (int u = 0; u < 8; u++) {
            float4 v = *(const float4*)(kp + 4 * u);
            kgs[(d0 + 4 * u + 0) * 128 + c] = v.x;
            kgs[(d0 + 4 * u + 1) * 128 + c] = v.y;
            kgs[(d0 + 4 * u + 2) * 128 + c] = v.z;
            kgs[(d0 + 4 * u + 3) * 128 + c] = v.w;
        }
    }
    __syncthreads();
    const int tx = t & 31, ty = t >> 5;
    float s[4][4];
    #pragma unroll
    for (int i = 0; i < 4; i++)
      #pragma unroll
      for (int j = 0; j < 4; j++) s[i][j] = 0.0f;
    #pragma unroll
    for (int d = 0; d < 64; d++) {
        float4 q4 = *(const float4*)&qgs[d * 32 + ty * 4];
        float4 k4 = *(const float4*)&kgs[d * 128 + tx * 4];
        float qa[4] = {q4.x, q4.y, q4.z, q4.w};
        float ka[4] = {k4.x, k4.y, k4.z, k4.w};
        #pragma unroll
        for (int i = 0; i < 4; i++)
          #pragma unroll
          for (int j = 0; j < 4; j++) s[i][j] += qa[i] * ka[j];
    }
    #pragma unroll
    for (int i = 0; i < 4; i++) {
        const int g = ty * 4 + i;
        float* gp = g_gw + (((size_t)(b * Hc + h) * Gc + g) * Sc) + st * 128 + tx * 4;
        *(float4*)gp = make_float4(s[i][0], s[i][1], s[i][2], s[i][3]);
    }
}

// ---------------- 5) row softmax over S for gw ----------------
__global__ __launch_bounds__(256) void global_softmax()
{
    float* p = g_gw + (size_t)blockIdx.x * Sc;
    __shared__ float sm2[8];
    const int t = threadIdx.x, lane = t & 31, wrp = t >> 5;
    float mx = NEG_INF;
    for (int i = t; i < Sc; i += 256) mx = fmaxf(mx, p[i]);
    #pragma unroll
    for (int o = 16; o; o >>= 1) mx = fmaxf(mx, __shfl_xor_sync(0xffffffffu, mx, o));
    if (lane == 0) sm2[wrp] = mx;
    __syncthreads();
    mx = sm2[0];
    #pragma unroll
    for (int i = 1; i < 8; i++) mx = fmaxf(mx, sm2[i]);
    __syncthreads();
    float sum = 0.0f;
    for (int i = t; i < Sc; i += 256) {
        const float e = __expf(p[i] - mx);
        p[i] = e;
        sum += e;
    }
    #pragma unroll
    for (int o = 16; o; o >>= 1) sum += __shfl_xor_sync(0xffffffffu, sum, o);
    if (lane == 0) sm2[wrp] = sum;
    __syncthreads();
    sum = 0.0f;
    #pragma unroll
    for (int i = 0; i < 8; i++) sum += sm2[i];
    const float inv = 1.0f / sum;
    for (int i = t; i < Sc; i += 256) p[i] *= inv;
}

// ---------------- 6) zero gattn accumulator ----------------
__global__ void zero_gattn()
{
    const int idx = blockIdx.x * 256 + threadIdx.x;
    if (idx < Bc * Gc * Ec) g_gattn[idx] = 0.0f;
}

// ---------------- 7) global PV ----------------
__global__ __launch_bounds__(256) void global_pv()
{
    const int sc = blockIdx.x;
    const int h  = blockIdx.y;
    const int b  = blockIdx.z;
    __shared__ float ps[32 * 128];
    const int t  = threadIdx.x;
    const int d  = t & 63;
    const int gq = t >> 6;
    float acc[8];
    #pragma unroll
    for (int gi = 0; gi < 8; gi++) acc[gi] = 0.0f;

    for (int s0 = sc * 512; s0 < sc * 512 + 512; s0 += 128) {
        __syncthreads();
        {
            const int g = t >> 3, sl = (t & 7) * 16;
            const float* src = g_gw + ((size_t)(b * Hc + h) * Gc + g) * Sc + s0 + sl;
            #pragma unroll
            for (int u = 0; u < 4; u++)
                *(float4*)&ps[g * 128 + sl + 4 * u] = *(const float4*)(src + 4 * u);
        }
        __syncthreads();
        for (int sl = 0; sl < 128; sl++) {
            const float vv = g_vg[(size_t)(b * Sc + s0 + sl) * Ec + h * 64 + d];
            #pragma unroll
            for (int gi = 0; gi < 8; gi++)
                acc[gi] += ps[(gq * 8 + gi) * 128 + sl] * vv;
        }
    }
    #pragma unroll
    for (int gi = 0; gi < 8; gi++)
        atomicAdd(&g_gattn[(size_t)(b * Gc + gq * 8 + gi) * Ec + h * 64 + d], acc[gi]);
}

// ---------------- 8) overwrite out[:, :G] with gattn ----------------
__global__ void write_global_rows(float* __restrict__ out)
{
    const int idx = blockIdx.x * 256 + threadIdx.x;
    if (idx < Bc * Gc * Ec) {
        const int e = idx % Ec;
        const int m = idx / Ec;
        const int b = m / Gc, g = m % Gc;
        out[(size_t)(b * Sc + g) * Ec + e] = g_gattn[idx];
    }
}

// ---------------- launch ----------------
extern "C" void kernel_launch(void* const* d_in, const int* in_sizes, int n_in,
                              void* d_out, int out_size)
{
    (void)out_size;
    const float* x    = (const float*)d_in[0];
    const int*   mask = (const int*)d_in[1];
    int wi = 2;
    if (n_in > 2 && in_sizes[2] == 1) wi = 3;
    const float* wq  = (const float*)d_in[wi + 0];
    const float* bq  = (const float*)d_in[wi + 1];
    const float* wk  = (const float*)d_in[wi + 2];
    const float* bk  = (const float*)d_in[wi + 3];
    const float* wv  = (const float*)d_in[wi + 4];
    const float* bv  = (const float*)d_in[wi + 5];
    const float* wqg = (const float*)d_in[wi + 6];
    const float* bqg = (const float*)d_in[wi + 7];
    const float* wkg = (const float*)d_in[wi + 8];
    const float* bkg = (const float*)d_in[wi + 9];
    const float* wvg = (const float*)d_in[wi + 10];
    const float* bvg = (const float*)d_in[wi + 11];
    float* out = (float*)d_out;

    cudaFuncSetAttribute(flash_mma, cudaFuncAttributeMaxDynamicSharedMemorySize, FLASH_SMEM);

    split_x<<<(Mrows * Ec) / 1024, 256>>>(x);
    split_wt<<<dim3(Ec / 32, Ec / 32, 6), 256>>>(wq, wk, wv, wkg, wvg, wqg);
    proj_mma<<<dim3(Ec / 128, Mrows / 128, 5), 256>>>(bq, bk, bv, bkg, bvg);
    transpose_v<<<dim3(Sc / 64, Hc, Bc), 256>>>();
    qg_mma<<<Ec / 128, 256>>>(bqg);

    flash_mma<<<dim3(Sc / 64, Hc, Bc), 128, FLASH_SMEM>>>(mask, out);

    dim3 gGS(Sc / 128, Hc, Bc);
    global_scores<<<gGS, 256>>>();
    global_softmax<<<Bc * Hc * Gc, 256>>>();
    zero_gattn<<<(Bc * Gc * Ec + 255) / 256, 256>>>();
    dim3 gPV(8, Hc, Bc);
    global_pv<<<gPV, 256>>>();
    write_global_rows<<<(Bc * Gc * Ec + 255) / 256, 256>>>(out);
}